// round 3
// baseline (speedup 1.0000x reference)
#include <cuda_runtime.h>
#include <cuda_bf16.h>
#include <cstdint>

// ---------------------------------------------------------------------------
// Problem constants
// ---------------------------------------------------------------------------
#define BATCH   4
#define SEQ     2048
#define DMODEL  512
#define DHID    2048
#define NHEADS  2
#define GSZ     256                 // head dim = DMODEL / NHEADS
#define MTOT    (BATCH * SEQ)       // 8192 rows

// ---------------------------------------------------------------------------
// Scratch (device globals; allocation-free per harness rules)
// ---------------------------------------------------------------------------
__device__ float g_q  [MTOT * DMODEL];
__device__ float g_k  [MTOT * DMODEL];
__device__ float g_v  [MTOT * DMODEL];
__device__ float g_att[MTOT * DMODEL];
__device__ float g_x  [MTOT * DMODEL];
__device__ float g_y  [MTOT * DMODEL];
__device__ float g_h  [MTOT * DHID];
__device__ float g_css[MTOT * DMODEL];
__device__ float g_cqq[MTOT * DMODEL];

// ---------------------------------------------------------------------------
// GEMM:  C[M,N] = epi( A[M,K] @ W[N,K]^T )   (torch Linear, no bias)
// 128x64 block tile, BK=16, 256 threads, 8x4 microtile per thread.
// EPI: 0 = none, 1 = relu
// ---------------------------------------------------------------------------
#define GBM 128
#define GBN 64
#define GBK 16
#define AST 132   // padded smem stride (rows of As)
#define BST 68

template <int EPI>
__global__ __launch_bounds__(256)
void gemm_nt(const float* __restrict__ A, const float* __restrict__ W,
             float* __restrict__ C, int M, int N, int K)
{
    __shared__ float As[GBK][AST];   // As[k][m]
    __shared__ float Bs[GBK][BST];   // Bs[k][n]

    const int bm = blockIdx.y * GBM;
    const int bn = blockIdx.x * GBN;
    const int tid = threadIdx.x;
    const int tm = tid >> 4;         // 0..15 -> rows tm*8
    const int tn = tid & 15;         // 0..15 -> cols tn*4

    // A tile loader: 128x16 floats = 512 float4 slots, 2 per thread
    const int s0 = tid, s1 = tid + 256;
    const int ar0 = s0 >> 2, ak0 = (s0 & 3) << 2;
    const int ar1 = s1 >> 2, ak1 = (s1 & 3) << 2;
    // B tile loader: 64x16 floats = 256 float4 slots, 1 per thread
    const int br = tid >> 2, bk = (tid & 3) << 2;

    const float* Ap = A + (size_t)bm * K;
    const float* Wp = W + (size_t)bn * K;

    float acc[8][4];
#pragma unroll
    for (int i = 0; i < 8; ++i)
#pragma unroll
        for (int j = 0; j < 4; ++j) acc[i][j] = 0.f;

    for (int k0 = 0; k0 < K; k0 += GBK) {
        const float4 a0 = *(const float4*)(Ap + (size_t)ar0 * K + k0 + ak0);
        const float4 a1 = *(const float4*)(Ap + (size_t)ar1 * K + k0 + ak1);
        const float4 b0 = *(const float4*)(Wp + (size_t)br  * K + k0 + bk);
        __syncthreads();
        As[ak0 + 0][ar0] = a0.x; As[ak0 + 1][ar0] = a0.y;
        As[ak0 + 2][ar0] = a0.z; As[ak0 + 3][ar0] = a0.w;
        As[ak1 + 0][ar1] = a1.x; As[ak1 + 1][ar1] = a1.y;
        As[ak1 + 2][ar1] = a1.z; As[ak1 + 3][ar1] = a1.w;
        Bs[bk + 0][br] = b0.x; Bs[bk + 1][br] = b0.y;
        Bs[bk + 2][br] = b0.z; Bs[bk + 3][br] = b0.w;
        __syncthreads();

#pragma unroll
        for (int kk = 0; kk < GBK; ++kk) {
            const float4 fa0 = *(const float4*)&As[kk][tm * 8];
            const float4 fa1 = *(const float4*)&As[kk][tm * 8 + 4];
            const float4 fb  = *(const float4*)&Bs[kk][tn * 4];
            const float av[8] = {fa0.x, fa0.y, fa0.z, fa0.w, fa1.x, fa1.y, fa1.z, fa1.w};
            const float bv[4] = {fb.x, fb.y, fb.z, fb.w};
#pragma unroll
            for (int i = 0; i < 8; ++i)
#pragma unroll
                for (int j = 0; j < 4; ++j) acc[i][j] += av[i] * bv[j];
        }
    }

#pragma unroll
    for (int i = 0; i < 8; ++i) {
        float4 r;
        r.x = acc[i][0]; r.y = acc[i][1]; r.z = acc[i][2]; r.w = acc[i][3];
        if (EPI == 1) {
            r.x = fmaxf(r.x, 0.f); r.y = fmaxf(r.y, 0.f);
            r.z = fmaxf(r.z, 0.f); r.w = fmaxf(r.w, 0.f);
        }
        *(float4*)&C[(size_t)(bm + tm * 8 + i) * N + bn + tn * 4] = r;
    }
}

// ---------------------------------------------------------------------------
// Flash attention (fp32, one pass, online softmax)
// Grid: (SEQ/64, NHEADS, BATCH), 256 threads.
// Q/K staged transposed [d][row] in smem, V row-major. O accumulated in regs.
// Softmax scale 1/sqrt(256) folded into Q load.
// ---------------------------------------------------------------------------
#define FBM 64
#define FBN 64
// smem floats: Qs(256*64) + Ks(256*64) + Vs(64*256) + S(64*64) + stats(3*64)
#define FA_SMEM_FLOATS (GSZ*FBM + GSZ*FBN + FBN*GSZ + FBM*FBN + 3*FBM)
#define FA_SMEM_BYTES  (FA_SMEM_FLOATS * 4)

extern __shared__ float fa_sm[];

__global__ __launch_bounds__(256)
void flash_kernel(const float* __restrict__ Q, const float* __restrict__ K,
                  const float* __restrict__ V, float* __restrict__ O)
{
    float* Qs  = fa_sm;                   // [d][row]  stride FBM
    float* Ks  = Qs  + GSZ * FBM;         // [d][row]  stride FBN
    float* Vs  = Ks  + GSZ * FBN;         // [row][d]  stride GSZ
    float* Ssm = Vs  + FBN * GSZ;         // [qr][kr]  stride FBN
    float* msm = Ssm + FBM * FBN;
    float* lsm = msm + FBM;
    float* csm = lsm + FBM;

    const int tid = threadIdx.x;
    const int qbase = blockIdx.x * FBM;
    const int h = blockIdx.y, b = blockIdx.z;
    const size_t bstride = (size_t)SEQ * DMODEL;
    const float* Qb = Q + b * bstride + h * GSZ;
    const float* Kb = K + b * bstride + h * GSZ;
    const float* Vb = V + b * bstride + h * GSZ;

    const int lrow = tid & 63;   // loader row (conflict-free transposed stores)
    const int ldch = tid >> 6;   // loader d-chunk 0..3 (64 d each)

    // stage Q tile (transposed + scaled by 1/16)
    {
        const float* src = Qb + (size_t)(qbase + lrow) * DMODEL + ldch * 64;
#pragma unroll
        for (int j = 0; j < 16; ++j) {
            const float4 v = *(const float4*)(src + j * 4);
            const int d = ldch * 64 + j * 4;
            Qs[(d + 0) * FBM + lrow] = v.x * 0.0625f;
            Qs[(d + 1) * FBM + lrow] = v.y * 0.0625f;
            Qs[(d + 2) * FBM + lrow] = v.z * 0.0625f;
            Qs[(d + 3) * FBM + lrow] = v.w * 0.0625f;
        }
    }
    if (tid < FBM) { msm[tid] = -1e30f; lsm[tid] = 0.f; }

    const int ty = tid >> 4;     // 0..15 -> S/O rows ty*4..+3
    const int tx = tid & 15;     // S cols tx*4..+3 ; O cols tx*16..+15

    float o[4][16];
#pragma unroll
    for (int i = 0; i < 4; ++i)
#pragma unroll
        for (int j = 0; j < 16; ++j) o[i][j] = 0.f;

    for (int kb = 0; kb < SEQ; kb += FBN) {
        __syncthreads();   // protect Ks/Vs from previous iteration's readers
        // stage K (transposed) and V (row-major)
        {
            const float* ksrc = Kb + (size_t)(kb + lrow) * DMODEL + ldch * 64;
#pragma unroll
            for (int j = 0; j < 16; ++j) {
                const float4 v = *(const float4*)(ksrc + j * 4);
                const int d = ldch * 64 + j * 4;
                Ks[(d + 0) * FBN + lrow] = v.x;
                Ks[(d + 1) * FBN + lrow] = v.y;
                Ks[(d + 2) * FBN + lrow] = v.z;
                Ks[(d + 3) * FBN + lrow] = v.w;
            }
            const float* vsrc = Vb + (size_t)(kb + lrow) * DMODEL + ldch * 64;
            float* vdst = Vs + lrow * GSZ + ldch * 64;
#pragma unroll
            for (int j = 0; j < 16; ++j)
                *(float4*)(vdst + j * 4) = *(const float4*)(vsrc + j * 4);
        }
        __syncthreads();

        // S = (Q*scale) @ K^T   (4x4 per thread)
        float s[4][4];
#pragma unroll
        for (int i = 0; i < 4; ++i)
#pragma unroll
            for (int j = 0; j < 4; ++j) s[i][j] = 0.f;

#pragma unroll 8
        for (int d = 0; d < GSZ; ++d) {
            const float4 q4 = *(const float4*)&Qs[d * FBM + ty * 4];
            const float4 k4 = *(const float4*)&Ks[d * FBN + tx * 4];
            const float qv[4] = {q4.x, q4.y, q4.z, q4.w};
            const float kv[4] = {k4.x, k4.y, k4.z, k4.w};
#pragma unroll
            for (int i = 0; i < 4; ++i)
#pragma unroll
                for (int j = 0; j < 4; ++j) s[i][j] += qv[i] * kv[j];
        }
#pragma unroll
        for (int i = 0; i < 4; ++i) {
            float4 r; r.x = s[i][0]; r.y = s[i][1]; r.z = s[i][2]; r.w = s[i][3];
            *(float4*)&Ssm[(ty * 4 + i) * FBN + tx * 4] = r;
        }
        __syncthreads();

        // online softmax: 4 lanes per row
        {
            const int row = tid >> 2, g = tid & 3;
            float* srow = Ssm + row * FBN + g * 16;
            float vals[16];
            float mx = -1e30f;
#pragma unroll
            for (int j = 0; j < 16; ++j) { vals[j] = srow[j]; mx = fmaxf(mx, vals[j]); }
            mx = fmaxf(mx, __shfl_xor_sync(0xffffffffu, mx, 1));
            mx = fmaxf(mx, __shfl_xor_sync(0xffffffffu, mx, 2));
            const float mold = msm[row];
            const float mnew = fmaxf(mold, mx);
            float sum = 0.f;
#pragma unroll
            for (int j = 0; j < 16; ++j) {
                const float p = __expf(vals[j] - mnew);
                srow[j] = p; sum += p;
            }
            sum += __shfl_xor_sync(0xffffffffu, sum, 1);
            sum += __shfl_xor_sync(0xffffffffu, sum, 2);
            if (g == 0) {
                const float c = __expf(mold - mnew);
                csm[row] = c;
                lsm[row] = lsm[row] * c + sum;
                msm[row] = mnew;
            }
        }
        __syncthreads();

        // rescale O, accumulate P @ V
        float cc[4];
#pragma unroll
        for (int i = 0; i < 4; ++i) cc[i] = csm[ty * 4 + i];
#pragma unroll
        for (int i = 0; i < 4; ++i)
#pragma unroll
            for (int j = 0; j < 16; ++j) o[i][j] *= cc[i];

#pragma unroll 2
        for (int kj = 0; kj < FBN; ++kj) {
            float p[4];
#pragma unroll
            for (int i = 0; i < 4; ++i) p[i] = Ssm[(ty * 4 + i) * FBN + kj];
            const float* vrow = Vs + kj * GSZ + tx * 16;
            const float4 v0 = *(const float4*)(vrow);
            const float4 v1 = *(const float4*)(vrow + 4);
            const float4 v2 = *(const float4*)(vrow + 8);
            const float4 v3 = *(const float4*)(vrow + 12);
            const float vv[16] = {v0.x, v0.y, v0.z, v0.w, v1.x, v1.y, v1.z, v1.w,
                                  v2.x, v2.y, v2.z, v2.w, v3.x, v3.y, v3.z, v3.w};
#pragma unroll
            for (int i = 0; i < 4; ++i)
#pragma unroll
                for (int j = 0; j < 16; ++j) o[i][j] += p[i] * vv[j];
        }
    }

    // finalize: divide by l, write out (concat heads back into channel dim)
    float linv[4];
#pragma unroll
    for (int i = 0; i < 4; ++i) linv[i] = 1.f / lsm[ty * 4 + i];

    float* Ob = O + b * bstride + h * GSZ;
#pragma unroll
    for (int i = 0; i < 4; ++i) {
        float* dst = Ob + (size_t)(qbase + ty * 4 + i) * DMODEL + tx * 16;
#pragma unroll
        for (int j4 = 0; j4 < 4; ++j4) {
            float4 r;
            r.x = o[i][j4 * 4 + 0] * linv[i];
            r.y = o[i][j4 * 4 + 1] * linv[i];
            r.z = o[i][j4 * 4 + 2] * linv[i];
            r.w = o[i][j4 * 4 + 3] * linv[i];
            *(float4*)(dst + j4 * 4) = r;
        }
    }
}

// ---------------------------------------------------------------------------
// out = LayerNorm(X (+R), g, b, eps)    one block per row, 128 threads
// ---------------------------------------------------------------------------
__global__ __launch_bounds__(128)
void add_ln_kernel(const float* __restrict__ X, const float* __restrict__ R,
                   const float* __restrict__ g, const float* __restrict__ bt,
                   float eps, float* __restrict__ out, int hasRes)
{
    const int row = blockIdx.x;
    const int tid = threadIdx.x;
    float4 v = *(const float4*)(X + (size_t)row * DMODEL + tid * 4);
    if (hasRes) {
        const float4 r = *(const float4*)(R + (size_t)row * DMODEL + tid * 4);
        v.x += r.x; v.y += r.y; v.z += r.z; v.w += r.w;
    }
    float s  = v.x + v.y + v.z + v.w;
    float sq = v.x * v.x + v.y * v.y + v.z * v.z + v.w * v.w;
#pragma unroll
    for (int off = 16; off; off >>= 1) {
        s  += __shfl_xor_sync(0xffffffffu, s,  off);
        sq += __shfl_xor_sync(0xffffffffu, sq, off);
    }
    __shared__ float ssum[4], ssq[4];
    const int w = tid >> 5, l = tid & 31;
    if (l == 0) { ssum[w] = s; ssq[w] = sq; }
    __syncthreads();
    s  = ssum[0] + ssum[1] + ssum[2] + ssum[3];
    sq = ssq[0]  + ssq[1]  + ssq[2]  + ssq[3];
    const float mean = s * (1.f / DMODEL);
    const float var  = sq * (1.f / DMODEL) - mean * mean;
    const float rstd = rsqrtf(var + eps);
    const float4 gg = *(const float4*)(g  + tid * 4);
    const float4 bb = *(const float4*)(bt + tid * 4);
    float4 r;
    r.x = (v.x - mean) * rstd * gg.x + bb.x;
    r.y = (v.y - mean) * rstd * gg.y + bb.y;
    r.z = (v.z - mean) * rstd * gg.z + bb.z;
    r.w = (v.w - mean) * rstd * gg.w + bb.w;
    *(float4*)(out + (size_t)row * DMODEL + tid * 4) = r;
}

// ---------------------------------------------------------------------------
// host side
// ---------------------------------------------------------------------------
extern "C" void kernel_launch(void* const* d_in, const int* in_sizes, int n_in,
                              void* d_out, int out_size)
{
    (void)in_sizes; (void)n_in; (void)out_size;
    const float* Fm   = (const float*)d_in[0];
    const float* Fs   = (const float*)d_in[1];
    const float* Fq   = (const float*)d_in[2];
    const float* Wq   = (const float*)d_in[3];
    const float* Wk   = (const float*)d_in[4];
    const float* Wv   = (const float*)d_in[5];
    const float* lng  = (const float*)d_in[6];
    const float* lnb  = (const float*)d_in[7];
    const float* w1   = (const float*)d_in[8];
    const float* w2   = (const float*)d_in[9];
    const float* flg  = (const float*)d_in[10];
    const float* flb  = (const float*)d_in[11];
    float* out = (float*)d_out;

    float *q, *k, *v, *att, *x, *y, *hh, *css, *cqq;
    cudaGetSymbolAddress((void**)&q,   g_q);
    cudaGetSymbolAddress((void**)&k,   g_k);
    cudaGetSymbolAddress((void**)&v,   g_v);
    cudaGetSymbolAddress((void**)&att, g_att);
    cudaGetSymbolAddress((void**)&x,   g_x);
    cudaGetSymbolAddress((void**)&y,   g_y);
    cudaGetSymbolAddress((void**)&hh,  g_h);
    cudaGetSymbolAddress((void**)&css, g_css);
    cudaGetSymbolAddress((void**)&cqq, g_cqq);

    cudaFuncSetAttribute(flash_kernel,
                         cudaFuncAttributeMaxDynamicSharedMemorySize,
                         FA_SMEM_BYTES);

    const dim3 gp(DMODEL / GBN, MTOT / GBM);      // projections / FFN2
    const dim3 gh(DHID   / GBN, MTOT / GBM);      // FFN1
    const dim3 ga(SEQ / FBM, NHEADS, BATCH);      // attention

    auto run_block = [&](int i, const float* Qp, const float* Kp,
                         const float* Vp, const float* Rp, float* op) {
        const size_t wOff  = (size_t)i * DMODEL * DMODEL;
        const size_t w1Off = (size_t)i * DHID * DMODEL;
        gemm_nt<0><<<gp, 256>>>(Qp, Wq + wOff, q, MTOT, DMODEL, DMODEL);
        gemm_nt<0><<<gp, 256>>>(Kp, Wk + wOff, k, MTOT, DMODEL, DMODEL);
        gemm_nt<0><<<gp, 256>>>(Vp, Wv + wOff, v, MTOT, DMODEL, DMODEL);
        flash_kernel<<<ga, 256, FA_SMEM_BYTES>>>(q, k, v, att);
        add_ln_kernel<<<MTOT, 128>>>(att, Rp, lng + i * DMODEL, lnb + i * DMODEL,
                                     1e-5f, x, 1);
        gemm_nt<1><<<gh, 256>>>(x,  w1 + w1Off, hh, MTOT, DHID, DMODEL);
        gemm_nt<0><<<gp, 256>>>(hh, w2 + w1Off, y,  MTOT, DMODEL, DHID);
        add_ln_kernel<<<MTOT, 128>>>(y, x, flg + i * DMODEL, flb + i * DMODEL,
                                     1e-6f, op, 1);
    };

    // css = blk(0, Fs, Fs, Fm, Fm); cqq = blk(1, Fq, Fq, Fq, Fq);
    // csq = blk(2, cqq, Fs, css, css)
    run_block(0, Fs,  Fs, Fm,  Fm,  css);
    run_block(1, Fq,  Fq, Fq,  Fq,  cqq);
    run_block(2, cqq, Fs, css, css, out);
}

// round 4
// speedup vs baseline: 1.5720x; 1.5720x over previous
#include <cuda_runtime.h>
#include <cuda_bf16.h>
#include <cstdint>

// ---------------------------------------------------------------------------
// Problem constants
// ---------------------------------------------------------------------------
#define BATCH   4
#define SEQ     2048
#define DMODEL  512
#define DHID    2048
#define NHEADS  2
#define GSZ     256                 // head dim
#define MTOT    (BATCH * SEQ)       // 8192 rows

// ---------------------------------------------------------------------------
// Scratch (device globals; allocation-free per harness rules)
// ---------------------------------------------------------------------------
__device__ float g_q  [MTOT * DMODEL];
__device__ float g_k  [MTOT * DMODEL];
__device__ float g_v  [MTOT * DMODEL];
__device__ float g_att[MTOT * DMODEL];
__device__ float g_x  [MTOT * DMODEL];
__device__ float g_y  [MTOT * DMODEL];
__device__ float g_h  [MTOT * DHID];
__device__ float g_css[MTOT * DMODEL];
__device__ float g_cqq[MTOT * DMODEL];

// ---------------------------------------------------------------------------
// helpers
// ---------------------------------------------------------------------------
__device__ __forceinline__ uint32_t sptr(const void* p) {
    return (uint32_t)__cvta_generic_to_shared(p);
}

__device__ __forceinline__ void ldm4(uint32_t a, uint32_t& r0, uint32_t& r1,
                                     uint32_t& r2, uint32_t& r3) {
    asm volatile("ldmatrix.sync.aligned.m8n8.x4.shared.b16 {%0,%1,%2,%3},[%4];"
                 : "=r"(r0), "=r"(r1), "=r"(r2), "=r"(r3) : "r"(a));
}

__device__ __forceinline__ void mma_bf16(float c[4], const uint32_t a[4],
                                         const uint32_t b[2]) {
    asm volatile(
        "mma.sync.aligned.m16n8k16.row.col.f32.bf16.bf16.f32 "
        "{%0,%1,%2,%3},{%4,%5,%6,%7},{%8,%9},{%0,%1,%2,%3};"
        : "+f"(c[0]), "+f"(c[1]), "+f"(c[2]), "+f"(c[3])
        : "r"(a[0]), "r"(a[1]), "r"(a[2]), "r"(a[3]), "r"(b[0]), "r"(b[1]));
}

// split fp32 -> bf16 hi + bf16 lo (a ~= hi + lo, residual error ~2^-17)
__device__ __forceinline__ void split2(float v, __nv_bfloat16& h, __nv_bfloat16& l) {
    h = __float2bfloat16(v);
    l = __float2bfloat16(v - __bfloat162float(h));
}

// ---------------------------------------------------------------------------
// Tensor-core GEMM:  C[M,N] = epi( A[M,K] @ W[N,K]^T )  fp32 in/out.
// Split-bf16 (3-pass) mma.sync m16n8k16. BM=128 BN=64 BK=32, 256 threads.
// Warp grid 4(m) x 2(n); warp tile 32x64? -> 32 rows x 32 cols.
// EPI: 0 none, 1 relu
// ---------------------------------------------------------------------------
#define TBM 128
#define TBN 64
#define TBK 32
#define TAS 40   // smem row stride in bf16 elems (pad 32 -> 40 for ldmatrix)

template <int EPI>
__global__ __launch_bounds__(256)
void gemm_tc(const float* __restrict__ A, const float* __restrict__ W,
             float* __restrict__ C, int M, int N, int K)
{
    __shared__ __nv_bfloat16 Ah[TBM * TAS], Al[TBM * TAS];
    __shared__ __nv_bfloat16 Bh[TBN * TAS], Bl[TBN * TAS];

    const int tid  = threadIdx.x;
    const int lane = tid & 31;
    const int wid  = tid >> 5;
    const int wm   = wid & 3;     // 4 m-warps * 32 rows = 128
    const int wn   = wid >> 2;    // 2 n-warps * 32 cols = 64
    const int bm   = blockIdx.y * TBM;
    const int bn   = blockIdx.x * TBN;

    float c[2][4][4];
#pragma unroll
    for (int mi = 0; mi < 2; ++mi)
#pragma unroll
        for (int ni = 0; ni < 4; ++ni)
#pragma unroll
            for (int e = 0; e < 4; ++e) c[mi][ni][e] = 0.f;

    // fragment lane geometry
    const int lmA = lane & 15;            // A row within m16
    const int lkA = (lane >> 4) << 3;     // A k-group (0/8)
    const int lnB = ((lane >> 4) & 1) * 8 + (lane & 7);  // B n within 16-group
    const int lkB = ((lane >> 3) & 1) * 8;               // B k-group (0/8)

    const uint32_t aAh = sptr(Ah), aAl = sptr(Al);
    const uint32_t aBh = sptr(Bh), aBl = sptr(Bl);

    for (int k0 = 0; k0 < K; k0 += TBK) {
        // --- gmem loads into regs (overlap previous compute) ---
        float4 av[4], bv[2];
#pragma unroll
        for (int j = 0; j < 4; ++j) {
            const int idx = tid + j * 256;          // 0..1023
            const int row = idx >> 3, kq = (idx & 7) << 2;
            av[j] = *(const float4*)(A + (size_t)(bm + row) * K + k0 + kq);
        }
#pragma unroll
        for (int j = 0; j < 2; ++j) {
            const int idx = tid + j * 256;          // 0..511
            const int row = idx >> 3, kq = (idx & 7) << 2;
            bv[j] = *(const float4*)(W + (size_t)(bn + row) * K + k0 + kq);
        }
        __syncthreads();
        // --- split + store to smem ---
#pragma unroll
        for (int j = 0; j < 4; ++j) {
            const int idx = tid + j * 256;
            const int row = idx >> 3, kq = (idx & 7) << 2;
            __nv_bfloat16 h0, h1, h2, h3, l0, l1, l2, l3;
            split2(av[j].x, h0, l0); split2(av[j].y, h1, l1);
            split2(av[j].z, h2, l2); split2(av[j].w, h3, l3);
            __nv_bfloat16* ph = Ah + row * TAS + kq;
            __nv_bfloat16* pl = Al + row * TAS + kq;
            *(__nv_bfloat162*)(ph)     = __nv_bfloat162(h0, h1);
            *(__nv_bfloat162*)(ph + 2) = __nv_bfloat162(h2, h3);
            *(__nv_bfloat162*)(pl)     = __nv_bfloat162(l0, l1);
            *(__nv_bfloat162*)(pl + 2) = __nv_bfloat162(l2, l3);
        }
#pragma unroll
        for (int j = 0; j < 2; ++j) {
            const int idx = tid + j * 256;
            const int row = idx >> 3, kq = (idx & 7) << 2;
            __nv_bfloat16 h0, h1, h2, h3, l0, l1, l2, l3;
            split2(bv[j].x, h0, l0); split2(bv[j].y, h1, l1);
            split2(bv[j].z, h2, l2); split2(bv[j].w, h3, l3);
            __nv_bfloat16* ph = Bh + row * TAS + kq;
            __nv_bfloat16* pl = Bl + row * TAS + kq;
            *(__nv_bfloat162*)(ph)     = __nv_bfloat162(h0, h1);
            *(__nv_bfloat162*)(ph + 2) = __nv_bfloat162(h2, h3);
            *(__nv_bfloat162*)(pl)     = __nv_bfloat162(l0, l1);
            *(__nv_bfloat162*)(pl + 2) = __nv_bfloat162(l2, l3);
        }
        __syncthreads();

        // --- two k16 steps of mma ---
#pragma unroll
        for (int ks = 0; ks < 2; ++ks) {
            const int kb = ks * 16;
            uint32_t ahf[2][4], alf[2][4];
#pragma unroll
            for (int mi = 0; mi < 2; ++mi) {
                const int m = wm * 32 + mi * 16 + lmA;
                const uint32_t off = (uint32_t)(m * TAS + kb + lkA) * 2;
                ldm4(aAh + off, ahf[mi][0], ahf[mi][1], ahf[mi][2], ahf[mi][3]);
                ldm4(aAl + off, alf[mi][0], alf[mi][1], alf[mi][2], alf[mi][3]);
            }
            uint32_t bhf[4][2], blf[4][2];
#pragma unroll
            for (int p = 0; p < 2; ++p) {
                const int n = wn * 32 + p * 16 + lnB;
                const uint32_t off = (uint32_t)(n * TAS + kb + lkB) * 2;
                ldm4(aBh + off, bhf[2*p][0], bhf[2*p][1], bhf[2*p+1][0], bhf[2*p+1][1]);
                ldm4(aBl + off, blf[2*p][0], blf[2*p][1], blf[2*p+1][0], blf[2*p+1][1]);
            }
#pragma unroll
            for (int mi = 0; mi < 2; ++mi)
#pragma unroll
                for (int ni = 0; ni < 4; ++ni) {
                    mma_bf16(c[mi][ni], ahf[mi], bhf[ni]);   // hi*hi
                    mma_bf16(c[mi][ni], ahf[mi], blf[ni]);   // hi*lo
                    mma_bf16(c[mi][ni], alf[mi], bhf[ni]);   // lo*hi
                }
        }
    }

    // --- epilogue ---
#pragma unroll
    for (int mi = 0; mi < 2; ++mi) {
        const int row0 = bm + wm * 32 + mi * 16 + (lane >> 2);
#pragma unroll
        for (int ni = 0; ni < 4; ++ni) {
            const int col = bn + wn * 32 + ni * 8 + ((lane & 3) << 1);
            float v0 = c[mi][ni][0], v1 = c[mi][ni][1];
            float v2 = c[mi][ni][2], v3 = c[mi][ni][3];
            if (EPI == 1) {
                v0 = fmaxf(v0, 0.f); v1 = fmaxf(v1, 0.f);
                v2 = fmaxf(v2, 0.f); v3 = fmaxf(v3, 0.f);
            }
            float2 r01; r01.x = v0; r01.y = v1;
            float2 r23; r23.x = v2; r23.y = v3;
            *(float2*)&C[(size_t)row0 * N + col]       = r01;
            *(float2*)&C[(size_t)(row0 + 8) * N + col] = r23;
        }
    }
}

// ---------------------------------------------------------------------------
// Flash attention (fp32 math, bf16-staged tiles -> 2 CTAs/SM)
// Grid: (SEQ/64, NHEADS, BATCH), 256 threads.
// ---------------------------------------------------------------------------
#define FBM 64
#define FBN 64
#define FA_SMEM_BYTES (GSZ*FBM*2 + GSZ*FBN*2 + FBN*GSZ*2 + FBM*FBN*4 + 3*FBM*4)

__device__ __forceinline__ void ld4bf(const __nv_bfloat16* p, float f[4]) {
    const uint2 u = *(const uint2*)p;
    const float2 a = __bfloat1622float2(*reinterpret_cast<const __nv_bfloat162*>(&u.x));
    const float2 b = __bfloat1622float2(*reinterpret_cast<const __nv_bfloat162*>(&u.y));
    f[0] = a.x; f[1] = a.y; f[2] = b.x; f[3] = b.y;
}

__device__ __forceinline__ void ld8bf(const __nv_bfloat16* p, float f[8]) {
    const uint4 u = *(const uint4*)p;
    const float2 a = __bfloat1622float2(*reinterpret_cast<const __nv_bfloat162*>(&u.x));
    const float2 b = __bfloat1622float2(*reinterpret_cast<const __nv_bfloat162*>(&u.y));
    const float2 cc = __bfloat1622float2(*reinterpret_cast<const __nv_bfloat162*>(&u.z));
    const float2 d = __bfloat1622float2(*reinterpret_cast<const __nv_bfloat162*>(&u.w));
    f[0] = a.x; f[1] = a.y; f[2] = b.x; f[3] = b.y;
    f[4] = cc.x; f[5] = cc.y; f[6] = d.x; f[7] = d.y;
}

extern __shared__ char fa_raw[];

__global__ __launch_bounds__(256, 2)
void flash_kernel(const float* __restrict__ Q, const float* __restrict__ K,
                  const float* __restrict__ V, float* __restrict__ O)
{
    __nv_bfloat16* Qs = (__nv_bfloat16*)fa_raw;        // [d][row] stride FBM
    __nv_bfloat16* Ks = Qs + GSZ * FBM;                // [d][row] stride FBN
    __nv_bfloat16* Vs = Ks + GSZ * FBN;                // [row][d] stride GSZ
    float* Ssm = (float*)(Vs + FBN * GSZ);             // [qr][kr] stride FBN
    float* msm = Ssm + FBM * FBN;
    float* lsm = msm + FBM;
    float* csm = lsm + FBM;

    const int tid = threadIdx.x;
    const int qbase = blockIdx.x * FBM;
    const int h = blockIdx.y, b = blockIdx.z;
    const size_t bstride = (size_t)SEQ * DMODEL;
    const float* Qb = Q + b * bstride + h * GSZ;
    const float* Kb = K + b * bstride + h * GSZ;
    const float* Vb = V + b * bstride + h * GSZ;

    const int lrow = tid & 63;
    const int ldch = tid >> 6;   // 0..3, each covers 64 d

    // stage Q (transposed, scaled by 1/16, bf16)
    {
        const float* src = Qb + (size_t)(qbase + lrow) * DMODEL + ldch * 64;
#pragma unroll
        for (int j = 0; j < 16; ++j) {
            const float4 v = *(const float4*)(src + j * 4);
            const int d = ldch * 64 + j * 4;
            Qs[(d + 0) * FBM + lrow] = __float2bfloat16(v.x * 0.0625f);
            Qs[(d + 1) * FBM + lrow] = __float2bfloat16(v.y * 0.0625f);
            Qs[(d + 2) * FBM + lrow] = __float2bfloat16(v.z * 0.0625f);
            Qs[(d + 3) * FBM + lrow] = __float2bfloat16(v.w * 0.0625f);
        }
    }
    if (tid < FBM) { msm[tid] = -1e30f; lsm[tid] = 0.f; }

    const int ty = tid >> 4;     // 0..15 -> rows ty*4..+3
    const int tx = tid & 15;     // S cols tx*4..+3 ; O cols tx*16..+15

    float o[4][16];
#pragma unroll
    for (int i = 0; i < 4; ++i)
#pragma unroll
        for (int j = 0; j < 16; ++j) o[i][j] = 0.f;

    for (int kb = 0; kb < SEQ; kb += FBN) {
        __syncthreads();
        // stage K (transposed bf16), V (row-major bf16)
        {
            const float* ksrc = Kb + (size_t)(kb + lrow) * DMODEL + ldch * 64;
#pragma unroll
            for (int j = 0; j < 16; ++j) {
                const float4 v = *(const float4*)(ksrc + j * 4);
                const int d = ldch * 64 + j * 4;
                Ks[(d + 0) * FBN + lrow] = __float2bfloat16(v.x);
                Ks[(d + 1) * FBN + lrow] = __float2bfloat16(v.y);
                Ks[(d + 2) * FBN + lrow] = __float2bfloat16(v.z);
                Ks[(d + 3) * FBN + lrow] = __float2bfloat16(v.w);
            }
            const float* vsrc = Vb + (size_t)(kb + lrow) * DMODEL + ldch * 64;
            __nv_bfloat16* vdst = Vs + lrow * GSZ + ldch * 64;
#pragma unroll
            for (int j = 0; j < 16; ++j) {
                const float4 v = *(const float4*)(vsrc + j * 4);
                __nv_bfloat162 p0(__float2bfloat16(v.x), __float2bfloat16(v.y));
                __nv_bfloat162 p1(__float2bfloat16(v.z), __float2bfloat16(v.w));
                *(__nv_bfloat162*)(vdst + j * 4)     = p0;
                *(__nv_bfloat162*)(vdst + j * 4 + 2) = p1;
            }
        }
        __syncthreads();

        // S = Q @ K^T
        float s[4][4];
#pragma unroll
        for (int i = 0; i < 4; ++i)
#pragma unroll
            for (int j = 0; j < 4; ++j) s[i][j] = 0.f;

#pragma unroll 8
        for (int d = 0; d < GSZ; ++d) {
            float qv[4], kv[4];
            ld4bf(&Qs[d * FBM + ty * 4], qv);
            ld4bf(&Ks[d * FBN + tx * 4], kv);
#pragma unroll
            for (int i = 0; i < 4; ++i)
#pragma unroll
                for (int j = 0; j < 4; ++j) s[i][j] += qv[i] * kv[j];
        }
#pragma unroll
        for (int i = 0; i < 4; ++i) {
            float4 r; r.x = s[i][0]; r.y = s[i][1]; r.z = s[i][2]; r.w = s[i][3];
            *(float4*)&Ssm[(ty * 4 + i) * FBN + tx * 4] = r;
        }
        __syncthreads();

        // online softmax (4 lanes per row)
        {
            const int row = tid >> 2, g = tid & 3;
            float* srow = Ssm + row * FBN + g * 16;
            float vals[16];
            float mx = -1e30f;
#pragma unroll
            for (int j = 0; j < 16; ++j) { vals[j] = srow[j]; mx = fmaxf(mx, vals[j]); }
            mx = fmaxf(mx, __shfl_xor_sync(0xffffffffu, mx, 1));
            mx = fmaxf(mx, __shfl_xor_sync(0xffffffffu, mx, 2));
            const float mold = msm[row];
            const float mnew = fmaxf(mold, mx);
            float sum = 0.f;
#pragma unroll
            for (int j = 0; j < 16; ++j) {
                const float p = __expf(vals[j] - mnew);
                srow[j] = p; sum += p;
            }
            sum += __shfl_xor_sync(0xffffffffu, sum, 1);
            sum += __shfl_xor_sync(0xffffffffu, sum, 2);
            if (g == 0) {
                const float cc = __expf(mold - mnew);
                csm[row] = cc;
                lsm[row] = lsm[row] * cc + sum;
                msm[row] = mnew;
            }
        }
        __syncthreads();

        // rescale O, accumulate P @ V
        float cc[4];
#pragma unroll
        for (int i = 0; i < 4; ++i) cc[i] = csm[ty * 4 + i];
#pragma unroll
        for (int i = 0; i < 4; ++i)
#pragma unroll
            for (int j = 0; j < 16; ++j) o[i][j] *= cc[i];

#pragma unroll 2
        for (int kj = 0; kj < FBN; ++kj) {
            float p[4];
#pragma unroll
            for (int i = 0; i < 4; ++i) p[i] = Ssm[(ty * 4 + i) * FBN + kj];
            float vv[16];
            ld8bf(&Vs[kj * GSZ + tx * 16], vv);
            ld8bf(&Vs[kj * GSZ + tx * 16 + 8], vv + 8);
#pragma unroll
            for (int i = 0; i < 4; ++i)
#pragma unroll
                for (int j = 0; j < 16; ++j) o[i][j] += p[i] * vv[j];
        }
    }

    // finalize
    float linv[4];
#pragma unroll
    for (int i = 0; i < 4; ++i) linv[i] = 1.f / lsm[ty * 4 + i];

    float* Ob = O + b * bstride + h * GSZ;
#pragma unroll
    for (int i = 0; i < 4; ++i) {
        float* dst = Ob + (size_t)(qbase + ty * 4 + i) * DMODEL + tx * 16;
#pragma unroll
        for (int j4 = 0; j4 < 4; ++j4) {
            float4 r;
            r.x = o[i][j4 * 4 + 0] * linv[i];
            r.y = o[i][j4 * 4 + 1] * linv[i];
            r.z = o[i][j4 * 4 + 2] * linv[i];
            r.w = o[i][j4 * 4 + 3] * linv[i];
            *(float4*)(dst + j4 * 4) = r;
        }
    }
}

// ---------------------------------------------------------------------------
// out = LayerNorm(X (+R), g, b, eps)    one block per row, 128 threads
// ---------------------------------------------------------------------------
__global__ __launch_bounds__(128)
void add_ln_kernel(const float* __restrict__ X, const float* __restrict__ R,
                   const float* __restrict__ g, const float* __restrict__ bt,
                   float eps, float* __restrict__ out, int hasRes)
{
    const int row = blockIdx.x;
    const int tid = threadIdx.x;
    float4 v = *(const float4*)(X + (size_t)row * DMODEL + tid * 4);
    if (hasRes) {
        const float4 r = *(const float4*)(R + (size_t)row * DMODEL + tid * 4);
        v.x += r.x; v.y += r.y; v.z += r.z; v.w += r.w;
    }
    float s  = v.x + v.y + v.z + v.w;
    float sq = v.x * v.x + v.y * v.y + v.z * v.z + v.w * v.w;
#pragma unroll
    for (int off = 16; off; off >>= 1) {
        s  += __shfl_xor_sync(0xffffffffu, s,  off);
        sq += __shfl_xor_sync(0xffffffffu, sq, off);
    }
    __shared__ float ssum[4], ssq[4];
    const int w = tid >> 5, l = tid & 31;
    if (l == 0) { ssum[w] = s; ssq[w] = sq; }
    __syncthreads();
    s  = ssum[0] + ssum[1] + ssum[2] + ssum[3];
    sq = ssq[0]  + ssq[1]  + ssq[2]  + ssq[3];
    const float mean = s * (1.f / DMODEL);
    const float var  = sq * (1.f / DMODEL) - mean * mean;
    const float rstd = rsqrtf(var + eps);
    const float4 gg = *(const float4*)(g  + tid * 4);
    const float4 bb = *(const float4*)(bt + tid * 4);
    float4 r;
    r.x = (v.x - mean) * rstd * gg.x + bb.x;
    r.y = (v.y - mean) * rstd * gg.y + bb.y;
    r.z = (v.z - mean) * rstd * gg.z + bb.z;
    r.w = (v.w - mean) * rstd * gg.w + bb.w;
    *(float4*)(out + (size_t)row * DMODEL + tid * 4) = r;
}

// ---------------------------------------------------------------------------
// host side
// ---------------------------------------------------------------------------
extern "C" void kernel_launch(void* const* d_in, const int* in_sizes, int n_in,
                              void* d_out, int out_size)
{
    (void)in_sizes; (void)n_in; (void)out_size;
    const float* Fm   = (const float*)d_in[0];
    const float* Fs   = (const float*)d_in[1];
    const float* Fq   = (const float*)d_in[2];
    const float* Wq   = (const float*)d_in[3];
    const float* Wk   = (const float*)d_in[4];
    const float* Wv   = (const float*)d_in[5];
    const float* lng  = (const float*)d_in[6];
    const float* lnb  = (const float*)d_in[7];
    const float* w1   = (const float*)d_in[8];
    const float* w2   = (const float*)d_in[9];
    const float* flg  = (const float*)d_in[10];
    const float* flb  = (const float*)d_in[11];
    float* out = (float*)d_out;

    float *q, *k, *v, *att, *x, *y, *hh, *css, *cqq;
    cudaGetSymbolAddress((void**)&q,   g_q);
    cudaGetSymbolAddress((void**)&k,   g_k);
    cudaGetSymbolAddress((void**)&v,   g_v);
    cudaGetSymbolAddress((void**)&att, g_att);
    cudaGetSymbolAddress((void**)&x,   g_x);
    cudaGetSymbolAddress((void**)&y,   g_y);
    cudaGetSymbolAddress((void**)&hh,  g_h);
    cudaGetSymbolAddress((void**)&css, g_css);
    cudaGetSymbolAddress((void**)&cqq, g_cqq);

    cudaFuncSetAttribute(flash_kernel,
                         cudaFuncAttributeMaxDynamicSharedMemorySize,
                         FA_SMEM_BYTES);

    const dim3 gp(DMODEL / TBN, MTOT / TBM);      // projections / FFN2
    const dim3 gh(DHID   / TBN, MTOT / TBM);      // FFN1
    const dim3 ga(SEQ / FBM, NHEADS, BATCH);      // attention

    auto run_block = [&](int i, const float* Qp, const float* Kp,
                         const float* Vp, const float* Rp, float* op) {
        const size_t wOff  = (size_t)i * DMODEL * DMODEL;
        const size_t w1Off = (size_t)i * DHID * DMODEL;
        gemm_tc<0><<<gp, 256>>>(Qp, Wq + wOff, q, MTOT, DMODEL, DMODEL);
        gemm_tc<0><<<gp, 256>>>(Kp, Wk + wOff, k, MTOT, DMODEL, DMODEL);
        gemm_tc<0><<<gp, 256>>>(Vp, Wv + wOff, v, MTOT, DMODEL, DMODEL);
        flash_kernel<<<ga, 256, FA_SMEM_BYTES>>>(q, k, v, att);
        add_ln_kernel<<<MTOT, 128>>>(att, Rp, lng + i * DMODEL, lnb + i * DMODEL,
                                     1e-5f, x, 1);
        gemm_tc<1><<<gh, 256>>>(x,  w1 + w1Off, hh, MTOT, DHID, DMODEL);
        gemm_tc<0><<<gp, 256>>>(hh, w2 + w1Off, y,  MTOT, DMODEL, DHID);
        add_ln_kernel<<<MTOT, 128>>>(y, x, flg + i * DMODEL, flb + i * DMODEL,
                                     1e-6f, op, 1);
    };

    // css = blk(0, Fs, Fs, Fm, Fm); cqq = blk(1, Fq, Fq, Fq, Fq);
    // csq = blk(2, cqq, Fs, css, css)
    run_block(0, Fs,  Fs, Fm,  Fm,  css);
    run_block(1, Fq,  Fq, Fq,  Fq,  cqq);
    run_block(2, cqq, Fs, css, css, out);
}

// round 5
// speedup vs baseline: 3.6622x; 2.3297x over previous
#include <cuda_runtime.h>
#include <cuda_bf16.h>
#include <cstdint>

// ---------------------------------------------------------------------------
// Problem constants
// ---------------------------------------------------------------------------
#define BATCH   4
#define SEQ     2048
#define DMODEL  512
#define DHID    2048
#define NHEADS  2
#define GSZ     256                 // head dim
#define MTOT    (BATCH * SEQ)       // 8192 rows

// ---------------------------------------------------------------------------
// Scratch (device globals; allocation-free per harness rules)
// ---------------------------------------------------------------------------
__device__ float g_q  [MTOT * DMODEL];
__device__ float g_k  [MTOT * DMODEL];
__device__ float g_v  [MTOT * DMODEL];
__device__ float g_att[MTOT * DMODEL];
__device__ float g_x  [MTOT * DMODEL];
__device__ float g_y  [MTOT * DMODEL];
__device__ float g_h  [MTOT * DHID];
__device__ float g_css[MTOT * DMODEL];
__device__ float g_cqq[MTOT * DMODEL];

// ---------------------------------------------------------------------------
// helpers
// ---------------------------------------------------------------------------
__device__ __forceinline__ uint32_t sptr(const void* p) {
    return (uint32_t)__cvta_generic_to_shared(p);
}

__device__ __forceinline__ void ldm4(uint32_t a, uint32_t& r0, uint32_t& r1,
                                     uint32_t& r2, uint32_t& r3) {
    asm volatile("ldmatrix.sync.aligned.m8n8.x4.shared.b16 {%0,%1,%2,%3},[%4];"
                 : "=r"(r0), "=r"(r1), "=r"(r2), "=r"(r3) : "r"(a));
}

__device__ __forceinline__ void mma_bf16(float c[4], const uint32_t a[4],
                                         const uint32_t b[2]) {
    asm volatile(
        "mma.sync.aligned.m16n8k16.row.col.f32.bf16.bf16.f32 "
        "{%0,%1,%2,%3},{%4,%5,%6,%7},{%8,%9},{%0,%1,%2,%3};"
        : "+f"(c[0]), "+f"(c[1]), "+f"(c[2]), "+f"(c[3])
        : "r"(a[0]), "r"(a[1]), "r"(a[2]), "r"(a[3]), "r"(b[0]), "r"(b[1]));
}

__device__ __forceinline__ float e2(float x) {
    float y; asm("ex2.approx.ftz.f32 %0,%1;" : "=f"(y) : "f"(x)); return y;
}

__device__ __forceinline__ uint32_t packbf(float a, float b) {
    const __nv_bfloat162 t = __float22bfloat162_rn(make_float2(a, b));
    return *reinterpret_cast<const uint32_t*>(&t);
}

// split fp32 -> bf16 hi + bf16 lo
__device__ __forceinline__ void split2(float v, __nv_bfloat16& h, __nv_bfloat16& l) {
    h = __float2bfloat16(v);
    l = __float2bfloat16(v - __bfloat162float(h));
}

// ---------------------------------------------------------------------------
// Tensor-core GEMM:  C[M,N] = epi( A[M,K] @ W[N,K]^T )  fp32 in/out.
// Split-bf16 (3-pass) mma.sync m16n8k16. BM=128 BN=64 BK=32, 256 threads.
// ---------------------------------------------------------------------------
#define TBM 128
#define TBN 64
#define TBK 32
#define TAS 40

template <int EPI>
__global__ __launch_bounds__(256)
void gemm_tc(const float* __restrict__ A, const float* __restrict__ W,
             float* __restrict__ C, int M, int N, int K)
{
    __shared__ __nv_bfloat16 Ah[TBM * TAS], Al[TBM * TAS];
    __shared__ __nv_bfloat16 Bh[TBN * TAS], Bl[TBN * TAS];

    const int tid  = threadIdx.x;
    const int lane = tid & 31;
    const int wid  = tid >> 5;
    const int wm   = wid & 3;
    const int wn   = wid >> 2;
    const int bm   = blockIdx.y * TBM;
    const int bn   = blockIdx.x * TBN;

    float c[2][4][4];
#pragma unroll
    for (int mi = 0; mi < 2; ++mi)
#pragma unroll
        for (int ni = 0; ni < 4; ++ni)
#pragma unroll
            for (int e = 0; e < 4; ++e) c[mi][ni][e] = 0.f;

    const int lmA = lane & 15;
    const int lkA = (lane >> 4) << 3;
    const int lnB = ((lane >> 4) & 1) * 8 + (lane & 7);
    const int lkB = ((lane >> 3) & 1) * 8;

    const uint32_t aAh = sptr(Ah), aAl = sptr(Al);
    const uint32_t aBh = sptr(Bh), aBl = sptr(Bl);

    for (int k0 = 0; k0 < K; k0 += TBK) {
        float4 av[4], bv[2];
#pragma unroll
        for (int j = 0; j < 4; ++j) {
            const int idx = tid + j * 256;
            const int row = idx >> 3, kq = (idx & 7) << 2;
            av[j] = *(const float4*)(A + (size_t)(bm + row) * K + k0 + kq);
        }
#pragma unroll
        for (int j = 0; j < 2; ++j) {
            const int idx = tid + j * 256;
            const int row = idx >> 3, kq = (idx & 7) << 2;
            bv[j] = *(const float4*)(W + (size_t)(bn + row) * K + k0 + kq);
        }
        __syncthreads();
#pragma unroll
        for (int j = 0; j < 4; ++j) {
            const int idx = tid + j * 256;
            const int row = idx >> 3, kq = (idx & 7) << 2;
            __nv_bfloat16 h0, h1, h2, h3, l0, l1, l2, l3;
            split2(av[j].x, h0, l0); split2(av[j].y, h1, l1);
            split2(av[j].z, h2, l2); split2(av[j].w, h3, l3);
            __nv_bfloat16* ph = Ah + row * TAS + kq;
            __nv_bfloat16* pl = Al + row * TAS + kq;
            *(__nv_bfloat162*)(ph)     = __nv_bfloat162(h0, h1);
            *(__nv_bfloat162*)(ph + 2) = __nv_bfloat162(h2, h3);
            *(__nv_bfloat162*)(pl)     = __nv_bfloat162(l0, l1);
            *(__nv_bfloat162*)(pl + 2) = __nv_bfloat162(l2, l3);
        }
#pragma unroll
        for (int j = 0; j < 2; ++j) {
            const int idx = tid + j * 256;
            const int row = idx >> 3, kq = (idx & 7) << 2;
            __nv_bfloat16 h0, h1, h2, h3, l0, l1, l2, l3;
            split2(bv[j].x, h0, l0); split2(bv[j].y, h1, l1);
            split2(bv[j].z, h2, l2); split2(bv[j].w, h3, l3);
            __nv_bfloat16* ph = Bh + row * TAS + kq;
            __nv_bfloat16* pl = Bl + row * TAS + kq;
            *(__nv_bfloat162*)(ph)     = __nv_bfloat162(h0, h1);
            *(__nv_bfloat162*)(ph + 2) = __nv_bfloat162(h2, h3);
            *(__nv_bfloat162*)(pl)     = __nv_bfloat162(l0, l1);
            *(__nv_bfloat162*)(pl + 2) = __nv_bfloat162(l2, l3);
        }
        __syncthreads();

#pragma unroll
        for (int ks = 0; ks < 2; ++ks) {
            const int kb = ks * 16;
            uint32_t ahf[2][4], alf[2][4];
#pragma unroll
            for (int mi = 0; mi < 2; ++mi) {
                const int m = wm * 32 + mi * 16 + lmA;
                const uint32_t off = (uint32_t)(m * TAS + kb + lkA) * 2;
                ldm4(aAh + off, ahf[mi][0], ahf[mi][1], ahf[mi][2], ahf[mi][3]);
                ldm4(aAl + off, alf[mi][0], alf[mi][1], alf[mi][2], alf[mi][3]);
            }
            uint32_t bhf[4][2], blf[4][2];
#pragma unroll
            for (int p = 0; p < 2; ++p) {
                const int n = wn * 32 + p * 16 + lnB;
                const uint32_t off = (uint32_t)(n * TAS + kb + lkB) * 2;
                ldm4(aBh + off, bhf[2*p][0], bhf[2*p][1], bhf[2*p+1][0], bhf[2*p+1][1]);
                ldm4(aBl + off, blf[2*p][0], blf[2*p][1], blf[2*p+1][0], blf[2*p+1][1]);
            }
#pragma unroll
            for (int mi = 0; mi < 2; ++mi)
#pragma unroll
                for (int ni = 0; ni < 4; ++ni) {
                    mma_bf16(c[mi][ni], ahf[mi], bhf[ni]);
                    mma_bf16(c[mi][ni], ahf[mi], blf[ni]);
                    mma_bf16(c[mi][ni], alf[mi], bhf[ni]);
                }
        }
    }

#pragma unroll
    for (int mi = 0; mi < 2; ++mi) {
        const int row0 = bm + wm * 32 + mi * 16 + (lane >> 2);
#pragma unroll
        for (int ni = 0; ni < 4; ++ni) {
            const int col = bn + wn * 32 + ni * 8 + ((lane & 3) << 1);
            float v0 = c[mi][ni][0], v1 = c[mi][ni][1];
            float v2 = c[mi][ni][2], v3 = c[mi][ni][3];
            if (EPI == 1) {
                v0 = fmaxf(v0, 0.f); v1 = fmaxf(v1, 0.f);
                v2 = fmaxf(v2, 0.f); v3 = fmaxf(v3, 0.f);
            }
            float2 r01; r01.x = v0; r01.y = v1;
            float2 r23; r23.x = v2; r23.y = v3;
            *(float2*)&C[(size_t)row0 * N + col]       = r01;
            *(float2*)&C[(size_t)(row0 + 8) * N + col] = r23;
        }
    }
}

// ---------------------------------------------------------------------------
// Tensor-core flash attention (FA2-style).
// CTA: 64 q-rows, 4 warps, each warp owns 16 rows x full d=256.
// K-blocks of 64. Qs[row][d], Ks[kcol][d] row-major bf16; Vt[d][kcol]
// transposed bf16 so PV's B operand is k-contiguous (same ldmatrix pattern
// as the GEMM). Softmax in registers, exp2 with log2(e) folded into Q scale.
// ---------------------------------------------------------------------------
#define FM  64
#define FN  64
#define FQS 264        // Qs/Ks row stride (bf16 elems)
#define VTS 72         // Vt row stride (bf16 elems)
#define FA_SMEM_BYTES ((FM*FQS + FN*FQS + GSZ*VTS) * 2)

extern __shared__ char fa_raw[];

__global__ __launch_bounds__(128, 2)
void flash_tc(const float* __restrict__ Q, const float* __restrict__ K,
              const float* __restrict__ V, float* __restrict__ O)
{
    __nv_bfloat16* Qs = (__nv_bfloat16*)fa_raw;      // [64][FQS]
    __nv_bfloat16* Ks = Qs + FM * FQS;               // [64][FQS]
    __nv_bfloat16* Vt = Ks + FN * FQS;               // [256][VTS]

    const int tid  = threadIdx.x;
    const int lane = tid & 31;
    const int w    = tid >> 5;          // warp 0..3 -> rows w*16..+15
    const int qbase = blockIdx.x * FM;
    const int h = blockIdx.y, b = blockIdx.z;
    const size_t bstride = (size_t)SEQ * DMODEL;
    const float* Qb = Q + b * bstride + h * GSZ;
    const float* Kb = K + b * bstride + h * GSZ;
    const float* Vb = V + b * bstride + h * GSZ;

    // fragment lane geometry (identical to gemm_tc)
    const int lmA = lane & 15;
    const int lkA = (lane >> 4) << 3;
    const int lnB = ((lane >> 4) & 1) * 8 + (lane & 7);
    const int lkB = ((lane >> 3) & 1) * 8;

    const uint32_t aQ = sptr(Qs) + (uint32_t)((w * 16 + lmA) * FQS + lkA) * 2;
    const uint32_t aK = sptr(Ks) + (uint32_t)(lnB * FQS + lkB) * 2;
    const uint32_t aV = sptr(Vt) + (uint32_t)(lnB * VTS + lkB) * 2;

    // stage Q (bf16, scaled by 1/sqrt(256) * log2(e))
    const float qscale = 0.0625f * 1.4426950408889634f;
    for (int j = 0; j < 32; ++j) {
        const int idx = tid + j * 128;           // 64 rows x 64 float4
        const int row = idx >> 6, f4 = idx & 63;
        const float4 v = *(const float4*)(Qb + (size_t)(qbase + row) * DMODEL + f4 * 4);
        __nv_bfloat16* p = Qs + row * FQS + f4 * 4;
        *(__nv_bfloat162*)(p)     = __float22bfloat162_rn(make_float2(v.x * qscale, v.y * qscale));
        *(__nv_bfloat162*)(p + 2) = __float22bfloat162_rn(make_float2(v.z * qscale, v.w * qscale));
    }

    float mA = -1e30f, mB = -1e30f, lA = 0.f, lB = 0.f;
    float o[32][4];
#pragma unroll
    for (int f = 0; f < 32; ++f)
#pragma unroll
        for (int e = 0; e < 4; ++e) o[f][e] = 0.f;

    const int vkcol = tid & 63;       // V transpose loader
    const int vdch  = tid >> 6;       // 0/1 -> d 0..127 / 128..255

    for (int kb = 0; kb < SEQ; kb += FN) {
        __syncthreads();
        // stage K row-major
        for (int j = 0; j < 32; ++j) {
            const int idx = tid + j * 128;
            const int row = idx >> 6, f4 = idx & 63;
            const float4 v = *(const float4*)(Kb + (size_t)(kb + row) * DMODEL + f4 * 4);
            __nv_bfloat16* p = Ks + row * FQS + f4 * 4;
            *(__nv_bfloat162*)(p)     = __float22bfloat162_rn(make_float2(v.x, v.y));
            *(__nv_bfloat162*)(p + 2) = __float22bfloat162_rn(make_float2(v.z, v.w));
        }
        // stage V transposed: Vt[d][kcol]
        {
            const float* vsrc = Vb + (size_t)(kb + vkcol) * DMODEL + vdch * 128;
#pragma unroll
            for (int j = 0; j < 32; ++j) {
                const float4 v = *(const float4*)(vsrc + j * 4);
                const int d = vdch * 128 + j * 4;
                Vt[(d + 0) * VTS + vkcol] = __float2bfloat16(v.x);
                Vt[(d + 1) * VTS + vkcol] = __float2bfloat16(v.y);
                Vt[(d + 2) * VTS + vkcol] = __float2bfloat16(v.z);
                Vt[(d + 3) * VTS + vkcol] = __float2bfloat16(v.w);
            }
        }
        __syncthreads();

        // --- S = Q @ K^T : m16 x n64, k=256 ---
        float s[8][4];
#pragma unroll
        for (int f = 0; f < 8; ++f)
#pragma unroll
            for (int e = 0; e < 4; ++e) s[f][e] = 0.f;

#pragma unroll
        for (int ks = 0; ks < 16; ++ks) {
            uint32_t af[4];
            ldm4(aQ + ks * 32, af[0], af[1], af[2], af[3]);
#pragma unroll
            for (int g = 0; g < 4; ++g) {
                uint32_t b0[2], b1[2];
                ldm4(aK + (uint32_t)(g * 16 * FQS) * 2 + ks * 32,
                     b0[0], b0[1], b1[0], b1[1]);
                mma_bf16(s[2 * g],     af, b0);
                mma_bf16(s[2 * g + 1], af, b1);
            }
        }

        // --- online softmax in registers (rows rA = w*16+(lane>>2), rB = +8) ---
        float mxA = -1e30f, mxB = -1e30f;
#pragma unroll
        for (int f = 0; f < 8; ++f) {
            mxA = fmaxf(mxA, fmaxf(s[f][0], s[f][1]));
            mxB = fmaxf(mxB, fmaxf(s[f][2], s[f][3]));
        }
        mxA = fmaxf(mxA, __shfl_xor_sync(0xffffffffu, mxA, 1));
        mxA = fmaxf(mxA, __shfl_xor_sync(0xffffffffu, mxA, 2));
        mxB = fmaxf(mxB, __shfl_xor_sync(0xffffffffu, mxB, 1));
        mxB = fmaxf(mxB, __shfl_xor_sync(0xffffffffu, mxB, 2));
        const float mnA = fmaxf(mA, mxA);
        const float mnB = fmaxf(mB, mxB);
        float sumA = 0.f, sumB = 0.f;
#pragma unroll
        for (int f = 0; f < 8; ++f) {
            s[f][0] = e2(s[f][0] - mnA); s[f][1] = e2(s[f][1] - mnA);
            s[f][2] = e2(s[f][2] - mnB); s[f][3] = e2(s[f][3] - mnB);
            sumA += s[f][0] + s[f][1];
            sumB += s[f][2] + s[f][3];
        }
        sumA += __shfl_xor_sync(0xffffffffu, sumA, 1);
        sumA += __shfl_xor_sync(0xffffffffu, sumA, 2);
        sumB += __shfl_xor_sync(0xffffffffu, sumB, 1);
        sumB += __shfl_xor_sync(0xffffffffu, sumB, 2);
        const float ccA = e2(mA - mnA);
        const float ccB = e2(mB - mnB);
        lA = lA * ccA + sumA; mA = mnA;
        lB = lB * ccB + sumB; mB = mnB;

        // rescale O
#pragma unroll
        for (int f = 0; f < 32; ++f) {
            o[f][0] *= ccA; o[f][1] *= ccA;
            o[f][2] *= ccB; o[f][3] *= ccB;
        }

        // --- O += P @ V : P m16 k64 (from regs), V via Vt ---
#pragma unroll
        for (int kf = 0; kf < 4; ++kf) {
            uint32_t ap[4];
            ap[0] = packbf(s[2 * kf][0],     s[2 * kf][1]);
            ap[1] = packbf(s[2 * kf][2],     s[2 * kf][3]);
            ap[2] = packbf(s[2 * kf + 1][0], s[2 * kf + 1][1]);
            ap[3] = packbf(s[2 * kf + 1][2], s[2 * kf + 1][3]);
#pragma unroll
            for (int g = 0; g < 16; ++g) {
                uint32_t b0[2], b1[2];
                ldm4(aV + (uint32_t)(g * 16 * VTS) * 2 + kf * 32,
                     b0[0], b0[1], b1[0], b1[1]);
                mma_bf16(o[2 * g],     ap, b0);
                mma_bf16(o[2 * g + 1], ap, b1);
            }
        }
    }

    // finalize
    const float liA = 1.f / lA;
    const float liB = 1.f / lB;
    const int rowA = qbase + w * 16 + (lane >> 2);
    float* Ob = O + b * bstride + h * GSZ;
#pragma unroll
    for (int f = 0; f < 32; ++f) {
        const int col = f * 8 + ((lane & 3) << 1);
        float2 rA; rA.x = o[f][0] * liA; rA.y = o[f][1] * liA;
        float2 rB; rB.x = o[f][2] * liB; rB.y = o[f][3] * liB;
        *(float2*)&Ob[(size_t)rowA * DMODEL + col]       = rA;
        *(float2*)&Ob[(size_t)(rowA + 8) * DMODEL + col] = rB;
    }
}

// ---------------------------------------------------------------------------
// out = LayerNorm(X (+R), g, b, eps)    one block per row, 128 threads
// ---------------------------------------------------------------------------
__global__ __launch_bounds__(128)
void add_ln_kernel(const float* __restrict__ X, const float* __restrict__ R,
                   const float* __restrict__ g, const float* __restrict__ bt,
                   float eps, float* __restrict__ out, int hasRes)
{
    const int row = blockIdx.x;
    const int tid = threadIdx.x;
    float4 v = *(const float4*)(X + (size_t)row * DMODEL + tid * 4);
    if (hasRes) {
        const float4 r = *(const float4*)(R + (size_t)row * DMODEL + tid * 4);
        v.x += r.x; v.y += r.y; v.z += r.z; v.w += r.w;
    }
    float s  = v.x + v.y + v.z + v.w;
    float sq = v.x * v.x + v.y * v.y + v.z * v.z + v.w * v.w;
#pragma unroll
    for (int off = 16; off; off >>= 1) {
        s  += __shfl_xor_sync(0xffffffffu, s,  off);
        sq += __shfl_xor_sync(0xffffffffu, sq, off);
    }
    __shared__ float ssum[4], ssq[4];
    const int w = tid >> 5, l = tid & 31;
    if (l == 0) { ssum[w] = s; ssq[w] = sq; }
    __syncthreads();
    s  = ssum[0] + ssum[1] + ssum[2] + ssum[3];
    sq = ssq[0]  + ssq[1]  + ssq[2]  + ssq[3];
    const float mean = s * (1.f / DMODEL);
    const float var  = sq * (1.f / DMODEL) - mean * mean;
    const float rstd = rsqrtf(var + eps);
    const float4 gg = *(const float4*)(g  + tid * 4);
    const float4 bb = *(const float4*)(bt + tid * 4);
    float4 r;
    r.x = (v.x - mean) * rstd * gg.x + bb.x;
    r.y = (v.y - mean) * rstd * gg.y + bb.y;
    r.z = (v.z - mean) * rstd * gg.z + bb.z;
    r.w = (v.w - mean) * rstd * gg.w + bb.w;
    *(float4*)(out + (size_t)row * DMODEL + tid * 4) = r;
}

// ---------------------------------------------------------------------------
// host side
// ---------------------------------------------------------------------------
extern "C" void kernel_launch(void* const* d_in, const int* in_sizes, int n_in,
                              void* d_out, int out_size)
{
    (void)in_sizes; (void)n_in; (void)out_size;
    const float* Fm   = (const float*)d_in[0];
    const float* Fs   = (const float*)d_in[1];
    const float* Fq   = (const float*)d_in[2];
    const float* Wq   = (const float*)d_in[3];
    const float* Wk   = (const float*)d_in[4];
    const float* Wv   = (const float*)d_in[5];
    const float* lng  = (const float*)d_in[6];
    const float* lnb  = (const float*)d_in[7];
    const float* w1   = (const float*)d_in[8];
    const float* w2   = (const float*)d_in[9];
    const float* flg  = (const float*)d_in[10];
    const float* flb  = (const float*)d_in[11];
    float* out = (float*)d_out;

    float *q, *k, *v, *att, *x, *y, *hh, *css, *cqq;
    cudaGetSymbolAddress((void**)&q,   g_q);
    cudaGetSymbolAddress((void**)&k,   g_k);
    cudaGetSymbolAddress((void**)&v,   g_v);
    cudaGetSymbolAddress((void**)&att, g_att);
    cudaGetSymbolAddress((void**)&x,   g_x);
    cudaGetSymbolAddress((void**)&y,   g_y);
    cudaGetSymbolAddress((void**)&hh,  g_h);
    cudaGetSymbolAddress((void**)&css, g_css);
    cudaGetSymbolAddress((void**)&cqq, g_cqq);

    cudaFuncSetAttribute(flash_tc,
                         cudaFuncAttributeMaxDynamicSharedMemorySize,
                         FA_SMEM_BYTES);

    const dim3 gp(DMODEL / TBN, MTOT / TBM);      // projections / FFN2
    const dim3 gh(DHID   / TBN, MTOT / TBM);      // FFN1
    const dim3 ga(SEQ / FM, NHEADS, BATCH);       // attention

    auto run_block = [&](int i, const float* Qp, const float* Kp,
                         const float* Vp, const float* Rp, float* op) {
        const size_t wOff  = (size_t)i * DMODEL * DMODEL;
        const size_t w1Off = (size_t)i * DHID * DMODEL;
        gemm_tc<0><<<gp, 256>>>(Qp, Wq + wOff, q, MTOT, DMODEL, DMODEL);
        gemm_tc<0><<<gp, 256>>>(Kp, Wk + wOff, k, MTOT, DMODEL, DMODEL);
        gemm_tc<0><<<gp, 256>>>(Vp, Wv + wOff, v, MTOT, DMODEL, DMODEL);
        flash_tc<<<ga, 128, FA_SMEM_BYTES>>>(q, k, v, att);
        add_ln_kernel<<<MTOT, 128>>>(att, Rp, lng + i * DMODEL, lnb + i * DMODEL,
                                     1e-5f, x, 1);
        gemm_tc<1><<<gh, 256>>>(x,  w1 + w1Off, hh, MTOT, DHID, DMODEL);
        gemm_tc<0><<<gp, 256>>>(hh, w2 + w1Off, y,  MTOT, DMODEL, DHID);
        add_ln_kernel<<<MTOT, 128>>>(y, x, flg + i * DMODEL, flb + i * DMODEL,
                                     1e-6f, op, 1);
    };

    // css = blk(0, Fs, Fs, Fm, Fm); cqq = blk(1, Fq, Fq, Fq, Fq);
    // csq = blk(2, cqq, Fs, css, css)
    run_block(0, Fs,  Fs, Fm,  Fm,  css);
    run_block(1, Fq,  Fq, Fq,  Fq,  cqq);
    run_block(2, cqq, Fs, css, css, out);
}

// round 6
// speedup vs baseline: 3.9880x; 1.0890x over previous
#include <cuda_runtime.h>
#include <cuda_bf16.h>
#include <cstdint>

// ---------------------------------------------------------------------------
// Problem constants
// ---------------------------------------------------------------------------
#define BATCH   4
#define SEQ     2048
#define DMODEL  512
#define DHID    2048
#define NHEADS  2
#define GSZ     256
#define MTOT    (BATCH * SEQ)       // 8192

// ---------------------------------------------------------------------------
// Scratch (device globals)
// ---------------------------------------------------------------------------
__device__ float g_q  [MTOT * DMODEL];
__device__ float g_k  [MTOT * DMODEL];
__device__ float g_v  [MTOT * DMODEL];
__device__ float g_att[MTOT * DMODEL];
__device__ float g_x  [MTOT * DMODEL];
__device__ float g_y  [MTOT * DMODEL];
__device__ float g_css[MTOT * DMODEL];
__device__ float g_cqq[MTOT * DMODEL];

// bf16 split buffers (hi / lo)
__device__ __nv_bfloat16 g_wqh[3*DMODEL*DMODEL], g_wql[3*DMODEL*DMODEL];
__device__ __nv_bfloat16 g_wkh[3*DMODEL*DMODEL], g_wkl[3*DMODEL*DMODEL];
__device__ __nv_bfloat16 g_wvh[3*DMODEL*DMODEL], g_wvl[3*DMODEL*DMODEL];
__device__ __nv_bfloat16 g_w1h[3*DHID*DMODEL],   g_w1l[3*DHID*DMODEL];
__device__ __nv_bfloat16 g_w2h[3*DMODEL*DHID],   g_w2l[3*DMODEL*DHID];
__device__ __nv_bfloat16 g_fmh[MTOT*DMODEL], g_fml[MTOT*DMODEL];
__device__ __nv_bfloat16 g_fsh[MTOT*DMODEL], g_fsl[MTOT*DMODEL];
__device__ __nv_bfloat16 g_fqh[MTOT*DMODEL], g_fql[MTOT*DMODEL];
__device__ __nv_bfloat16 g_cssh[MTOT*DMODEL], g_cssl[MTOT*DMODEL];
__device__ __nv_bfloat16 g_cqqh[MTOT*DMODEL], g_cqql[MTOT*DMODEL];
__device__ __nv_bfloat16 g_xh[MTOT*DMODEL],  g_xl[MTOT*DMODEL];
__device__ __nv_bfloat16 g_hh[MTOT*DHID],    g_hl[MTOT*DHID];

// ---------------------------------------------------------------------------
// helpers
// ---------------------------------------------------------------------------
__device__ __forceinline__ uint32_t sptr(const void* p) {
    return (uint32_t)__cvta_generic_to_shared(p);
}
__device__ __forceinline__ void ldm4(uint32_t a, uint32_t& r0, uint32_t& r1,
                                     uint32_t& r2, uint32_t& r3) {
    asm volatile("ldmatrix.sync.aligned.m8n8.x4.shared.b16 {%0,%1,%2,%3},[%4];"
                 : "=r"(r0), "=r"(r1), "=r"(r2), "=r"(r3) : "r"(a));
}
__device__ __forceinline__ void mma_bf16(float c[4], const uint32_t a[4],
                                         const uint32_t b[2]) {
    asm volatile(
        "mma.sync.aligned.m16n8k16.row.col.f32.bf16.bf16.f32 "
        "{%0,%1,%2,%3},{%4,%5,%6,%7},{%8,%9},{%0,%1,%2,%3};"
        : "+f"(c[0]), "+f"(c[1]), "+f"(c[2]), "+f"(c[3])
        : "r"(a[0]), "r"(a[1]), "r"(a[2]), "r"(a[3]), "r"(b[0]), "r"(b[1]));
}
__device__ __forceinline__ float e2(float x) {
    float y; asm("ex2.approx.ftz.f32 %0,%1;" : "=f"(y) : "f"(x)); return y;
}
__device__ __forceinline__ uint32_t packbf(float a, float b) {
    const __nv_bfloat162 t = __float22bfloat162_rn(make_float2(a, b));
    return *reinterpret_cast<const uint32_t*>(&t);
}
__device__ __forceinline__ void split2(float v, __nv_bfloat16& h, __nv_bfloat16& l) {
    h = __float2bfloat16(v);
    l = __float2bfloat16(v - __bfloat162float(h));
}
__device__ __forceinline__ void cpa16(uint32_t s, const void* g) {
    asm volatile("cp.async.cg.shared.global [%0],[%1],16;" :: "r"(s), "l"(g));
}
__device__ __forceinline__ void cpa_commit() {
    asm volatile("cp.async.commit_group;");
}
template <int N>
__device__ __forceinline__ void cpa_wait() {
    asm volatile("cp.async.wait_group %0;" :: "n"(N));
}

// ---------------------------------------------------------------------------
// split kernel: fp32 -> (hi, lo) bf16
// ---------------------------------------------------------------------------
__global__ __launch_bounds__(256)
void split_kernel(const float* __restrict__ src, __nv_bfloat16* __restrict__ h,
                  __nv_bfloat16* __restrict__ l, int n4)
{
    const int i = blockIdx.x * 256 + threadIdx.x;
    if (i >= n4) return;
    const float4 v = *(const float4*)(src + (size_t)i * 4);
    __nv_bfloat16 h0, h1, h2, h3, l0, l1, l2, l3;
    split2(v.x, h0, l0); split2(v.y, h1, l1);
    split2(v.z, h2, l2); split2(v.w, h3, l3);
    *(__nv_bfloat162*)(h + (size_t)i * 4)     = __nv_bfloat162(h0, h1);
    *(__nv_bfloat162*)(h + (size_t)i * 4 + 2) = __nv_bfloat162(h2, h3);
    *(__nv_bfloat162*)(l + (size_t)i * 4)     = __nv_bfloat162(l0, l1);
    *(__nv_bfloat162*)(l + (size_t)i * 4 + 2) = __nv_bfloat162(l2, l3);
}

// ---------------------------------------------------------------------------
// Pure-bf16 split GEMM:  C = epi( (Ah+Al)[M,K] @ (Bh+Bl)[N,K]^T )
// 128x128x32 tiles, 256 threads, cp.async double-buffered smem.
// OUT: 0 -> fp32 C;  1 -> relu + split to (Ch, Cl) bf16
// ---------------------------------------------------------------------------
#define TBM 128
#define TBN 128
#define TBK 32
#define TAS 40
#define REGB  (TBM * TAS * 2)      // 10240 bytes per matrix region
#define BUFSZ (4 * REGB)           // Ah | Al | Bh | Bl
#define GEMM_SMEM (2 * BUFSZ)      // 81920

extern __shared__ char gsm[];

template <int OUT>
__global__ __launch_bounds__(256)
void gemm_bf(const __nv_bfloat16* __restrict__ Agh, const __nv_bfloat16* __restrict__ Agl,
             const __nv_bfloat16* __restrict__ Bgh, const __nv_bfloat16* __restrict__ Bgl,
             float* __restrict__ C, __nv_bfloat16* __restrict__ Ch,
             __nv_bfloat16* __restrict__ Cl, int M, int N, int K)
{
    const int tid  = threadIdx.x;
    const int lane = tid & 31;
    const int wid  = tid >> 5;
    const int wm   = wid & 3;        // 4 m-warps * 32 rows
    const int wn   = wid >> 2;       // 2 n-warps * 64 cols
    const int bm   = blockIdx.y * TBM;
    const int bn   = blockIdx.x * TBN;

    const uint32_t sbase = sptr(gsm);

    // loader geometry: 512 16B-chunks per region, 2 per thread
    const int c0 = tid, c1 = tid + 256;
    const int r0 = c0 >> 2, kc0 = (c0 & 3) << 3;
    const int r1 = c1 >> 2, kc1 = (c1 & 3) << 3;
    const uint32_t s0 = (uint32_t)(r0 * TAS + kc0) * 2;
    const uint32_t s1 = (uint32_t)(r1 * TAS + kc1) * 2;

    auto load_tile = [&](int buf, int k0) {
        const uint32_t b = sbase + buf * BUFSZ;
        cpa16(b + s0,             Agh + (size_t)(bm + r0) * K + k0 + kc0);
        cpa16(b + s1,             Agh + (size_t)(bm + r1) * K + k0 + kc1);
        cpa16(b + REGB + s0,      Agl + (size_t)(bm + r0) * K + k0 + kc0);
        cpa16(b + REGB + s1,      Agl + (size_t)(bm + r1) * K + k0 + kc1);
        cpa16(b + 2 * REGB + s0,  Bgh + (size_t)(bn + r0) * K + k0 + kc0);
        cpa16(b + 2 * REGB + s1,  Bgh + (size_t)(bn + r1) * K + k0 + kc1);
        cpa16(b + 3 * REGB + s0,  Bgl + (size_t)(bn + r0) * K + k0 + kc0);
        cpa16(b + 3 * REGB + s1,  Bgl + (size_t)(bn + r1) * K + k0 + kc1);
        cpa_commit();
    };

    float c[2][8][4];
#pragma unroll
    for (int mi = 0; mi < 2; ++mi)
#pragma unroll
        for (int ni = 0; ni < 8; ++ni)
#pragma unroll
            for (int e = 0; e < 4; ++e) c[mi][ni][e] = 0.f;

    // fragment lane geometry (validated pattern)
    const int lmA = lane & 15;
    const int lkA = (lane >> 4) << 3;
    const int lnB = ((lane >> 4) & 1) * 8 + (lane & 7);
    const int lkB = ((lane >> 3) & 1) * 8;
    const uint32_t relA = (uint32_t)((wm * 32 + lmA) * TAS + lkA) * 2;
    const uint32_t relB = (uint32_t)((wn * 64 + lnB) * TAS + lkB) * 2;

    const int niter = K / TBK;
    load_tile(0, 0);

    for (int it = 0; it < niter; ++it) {
        const int cur = it & 1;
        if (it + 1 < niter) { load_tile(cur ^ 1, (it + 1) * TBK); cpa_wait<1>(); }
        else cpa_wait<0>();
        __syncthreads();

        const uint32_t b = sbase + cur * BUFSZ;
        const uint32_t aAh = b + relA,            aAl = b + REGB + relA;
        const uint32_t aBh = b + 2 * REGB + relB, aBl = b + 3 * REGB + relB;

#pragma unroll
        for (int ks = 0; ks < 2; ++ks) {
            const uint32_t ko = ks * 32;
            uint32_t ahf[2][4], alf[2][4];
#pragma unroll
            for (int mi = 0; mi < 2; ++mi) {
                ldm4(aAh + mi * (16 * TAS * 2) + ko,
                     ahf[mi][0], ahf[mi][1], ahf[mi][2], ahf[mi][3]);
                ldm4(aAl + mi * (16 * TAS * 2) + ko,
                     alf[mi][0], alf[mi][1], alf[mi][2], alf[mi][3]);
            }
            uint32_t bhf[8][2], blf[8][2];
#pragma unroll
            for (int p = 0; p < 4; ++p) {
                ldm4(aBh + p * (16 * TAS * 2) + ko,
                     bhf[2*p][0], bhf[2*p][1], bhf[2*p+1][0], bhf[2*p+1][1]);
                ldm4(aBl + p * (16 * TAS * 2) + ko,
                     blf[2*p][0], blf[2*p][1], blf[2*p+1][0], blf[2*p+1][1]);
            }
#pragma unroll
            for (int mi = 0; mi < 2; ++mi)
#pragma unroll
                for (int ni = 0; ni < 8; ++ni) {
                    mma_bf16(c[mi][ni], ahf[mi], bhf[ni]);
                    mma_bf16(c[mi][ni], ahf[mi], blf[ni]);
                    mma_bf16(c[mi][ni], alf[mi], bhf[ni]);
                }
        }
        __syncthreads();
    }

    // epilogue
#pragma unroll
    for (int mi = 0; mi < 2; ++mi) {
        const int row0 = bm + wm * 32 + mi * 16 + (lane >> 2);
#pragma unroll
        for (int ni = 0; ni < 8; ++ni) {
            const int col = bn + wn * 64 + ni * 8 + ((lane & 3) << 1);
            float v0 = c[mi][ni][0], v1 = c[mi][ni][1];
            float v2 = c[mi][ni][2], v3 = c[mi][ni][3];
            if (OUT == 0) {
                float2 a; a.x = v0; a.y = v1;
                float2 bq; bq.x = v2; bq.y = v3;
                *(float2*)&C[(size_t)row0 * N + col]       = a;
                *(float2*)&C[(size_t)(row0 + 8) * N + col] = bq;
            } else {
                v0 = fmaxf(v0, 0.f); v1 = fmaxf(v1, 0.f);
                v2 = fmaxf(v2, 0.f); v3 = fmaxf(v3, 0.f);
                __nv_bfloat16 h0, h1, h2, h3, l0, l1, l2, l3;
                split2(v0, h0, l0); split2(v1, h1, l1);
                split2(v2, h2, l2); split2(v3, h3, l3);
                *(__nv_bfloat162*)&Ch[(size_t)row0 * N + col]       = __nv_bfloat162(h0, h1);
                *(__nv_bfloat162*)&Cl[(size_t)row0 * N + col]       = __nv_bfloat162(l0, l1);
                *(__nv_bfloat162*)&Ch[(size_t)(row0 + 8) * N + col] = __nv_bfloat162(h2, h3);
                *(__nv_bfloat162*)&Cl[(size_t)(row0 + 8) * N + col] = __nv_bfloat162(l2, l3);
            }
        }
    }
}

// ---------------------------------------------------------------------------
// Tensor-core flash attention (unchanged from R5 — 336us, validated)
// ---------------------------------------------------------------------------
#define FM  64
#define FN  64
#define FQS 264
#define VTS 72
#define FA_SMEM_BYTES ((FM*FQS + FN*FQS + GSZ*VTS) * 2)

extern __shared__ char fa_raw[];

__global__ __launch_bounds__(128, 2)
void flash_tc(const float* __restrict__ Q, const float* __restrict__ K,
              const float* __restrict__ V, float* __restrict__ O)
{
    __nv_bfloat16* Qs = (__nv_bfloat16*)fa_raw;
    __nv_bfloat16* Ks = Qs + FM * FQS;
    __nv_bfloat16* Vt = Ks + FN * FQS;

    const int tid  = threadIdx.x;
    const int lane = tid & 31;
    const int w    = tid >> 5;
    const int qbase = blockIdx.x * FM;
    const int h = blockIdx.y, b = blockIdx.z;
    const size_t bstride = (size_t)SEQ * DMODEL;
    const float* Qb = Q + b * bstride + h * GSZ;
    const float* Kb = K + b * bstride + h * GSZ;
    const float* Vb = V + b * bstride + h * GSZ;

    const int lmA = lane & 15;
    const int lkA = (lane >> 4) << 3;
    const int lnB = ((lane >> 4) & 1) * 8 + (lane & 7);
    const int lkB = ((lane >> 3) & 1) * 8;

    const uint32_t aQ = sptr(Qs) + (uint32_t)((w * 16 + lmA) * FQS + lkA) * 2;
    const uint32_t aK = sptr(Ks) + (uint32_t)(lnB * FQS + lkB) * 2;
    const uint32_t aV = sptr(Vt) + (uint32_t)(lnB * VTS + lkB) * 2;

    const float qscale = 0.0625f * 1.4426950408889634f;
    for (int j = 0; j < 32; ++j) {
        const int idx = tid + j * 128;
        const int row = idx >> 6, f4 = idx & 63;
        const float4 v = *(const float4*)(Qb + (size_t)(qbase + row) * DMODEL + f4 * 4);
        __nv_bfloat16* p = Qs + row * FQS + f4 * 4;
        *(__nv_bfloat162*)(p)     = __float22bfloat162_rn(make_float2(v.x * qscale, v.y * qscale));
        *(__nv_bfloat162*)(p + 2) = __float22bfloat162_rn(make_float2(v.z * qscale, v.w * qscale));
    }

    float mA = -1e30f, mB = -1e30f, lA = 0.f, lB = 0.f;
    float o[32][4];
#pragma unroll
    for (int f = 0; f < 32; ++f)
#pragma unroll
        for (int e = 0; e < 4; ++e) o[f][e] = 0.f;

    const int vkcol = tid & 63;
    const int vdch  = tid >> 6;

    for (int kb = 0; kb < SEQ; kb += FN) {
        __syncthreads();
        for (int j = 0; j < 32; ++j) {
            const int idx = tid + j * 128;
            const int row = idx >> 6, f4 = idx & 63;
            const float4 v = *(const float4*)(Kb + (size_t)(kb + row) * DMODEL + f4 * 4);
            __nv_bfloat16* p = Ks + row * FQS + f4 * 4;
            *(__nv_bfloat162*)(p)     = __float22bfloat162_rn(make_float2(v.x, v.y));
            *(__nv_bfloat162*)(p + 2) = __float22bfloat162_rn(make_float2(v.z, v.w));
        }
        {
            const float* vsrc = Vb + (size_t)(kb + vkcol) * DMODEL + vdch * 128;
#pragma unroll
            for (int j = 0; j < 32; ++j) {
                const float4 v = *(const float4*)(vsrc + j * 4);
                const int d = vdch * 128 + j * 4;
                Vt[(d + 0) * VTS + vkcol] = __float2bfloat16(v.x);
                Vt[(d + 1) * VTS + vkcol] = __float2bfloat16(v.y);
                Vt[(d + 2) * VTS + vkcol] = __float2bfloat16(v.z);
                Vt[(d + 3) * VTS + vkcol] = __float2bfloat16(v.w);
            }
        }
        __syncthreads();

        float s[8][4];
#pragma unroll
        for (int f = 0; f < 8; ++f)
#pragma unroll
            for (int e = 0; e < 4; ++e) s[f][e] = 0.f;

#pragma unroll
        for (int ks = 0; ks < 16; ++ks) {
            uint32_t af[4];
            ldm4(aQ + ks * 32, af[0], af[1], af[2], af[3]);
#pragma unroll
            for (int g = 0; g < 4; ++g) {
                uint32_t b0[2], b1[2];
                ldm4(aK + (uint32_t)(g * 16 * FQS) * 2 + ks * 32,
                     b0[0], b0[1], b1[0], b1[1]);
                mma_bf16(s[2 * g],     af, b0);
                mma_bf16(s[2 * g + 1], af, b1);
            }
        }

        float mxA = -1e30f, mxB = -1e30f;
#pragma unroll
        for (int f = 0; f < 8; ++f) {
            mxA = fmaxf(mxA, fmaxf(s[f][0], s[f][1]));
            mxB = fmaxf(mxB, fmaxf(s[f][2], s[f][3]));
        }
        mxA = fmaxf(mxA, __shfl_xor_sync(0xffffffffu, mxA, 1));
        mxA = fmaxf(mxA, __shfl_xor_sync(0xffffffffu, mxA, 2));
        mxB = fmaxf(mxB, __shfl_xor_sync(0xffffffffu, mxB, 1));
        mxB = fmaxf(mxB, __shfl_xor_sync(0xffffffffu, mxB, 2));
        const float mnA = fmaxf(mA, mxA);
        const float mnB = fmaxf(mB, mxB);
        float sumA = 0.f, sumB = 0.f;
#pragma unroll
        for (int f = 0; f < 8; ++f) {
            s[f][0] = e2(s[f][0] - mnA); s[f][1] = e2(s[f][1] - mnA);
            s[f][2] = e2(s[f][2] - mnB); s[f][3] = e2(s[f][3] - mnB);
            sumA += s[f][0] + s[f][1];
            sumB += s[f][2] + s[f][3];
        }
        sumA += __shfl_xor_sync(0xffffffffu, sumA, 1);
        sumA += __shfl_xor_sync(0xffffffffu, sumA, 2);
        sumB += __shfl_xor_sync(0xffffffffu, sumB, 1);
        sumB += __shfl_xor_sync(0xffffffffu, sumB, 2);
        const float ccA = e2(mA - mnA);
        const float ccB = e2(mB - mnB);
        lA = lA * ccA + sumA; mA = mnA;
        lB = lB * ccB + sumB; mB = mnB;

#pragma unroll
        for (int f = 0; f < 32; ++f) {
            o[f][0] *= ccA; o[f][1] *= ccA;
            o[f][2] *= ccB; o[f][3] *= ccB;
        }

#pragma unroll
        for (int kf = 0; kf < 4; ++kf) {
            uint32_t ap[4];
            ap[0] = packbf(s[2 * kf][0],     s[2 * kf][1]);
            ap[1] = packbf(s[2 * kf][2],     s[2 * kf][3]);
            ap[2] = packbf(s[2 * kf + 1][0], s[2 * kf + 1][1]);
            ap[3] = packbf(s[2 * kf + 1][2], s[2 * kf + 1][3]);
#pragma unroll
            for (int g = 0; g < 16; ++g) {
                uint32_t b0[2], b1[2];
                ldm4(aV + (uint32_t)(g * 16 * VTS) * 2 + kf * 32,
                     b0[0], b0[1], b1[0], b1[1]);
                mma_bf16(o[2 * g],     ap, b0);
                mma_bf16(o[2 * g + 1], ap, b1);
            }
        }
    }

    const float liA = 1.f / lA;
    const float liB = 1.f / lB;
    const int rowA = qbase + w * 16 + (lane >> 2);
    float* Ob = O + b * bstride + h * GSZ;
#pragma unroll
    for (int f = 0; f < 32; ++f) {
        const int col = f * 8 + ((lane & 3) << 1);
        float2 rA; rA.x = o[f][0] * liA; rA.y = o[f][1] * liA;
        float2 rB; rB.x = o[f][2] * liB; rB.y = o[f][3] * liB;
        *(float2*)&Ob[(size_t)rowA * DMODEL + col]       = rA;
        *(float2*)&Ob[(size_t)(rowA + 8) * DMODEL + col] = rB;
    }
}

// ---------------------------------------------------------------------------
// out = LayerNorm(X + R); optionally also emit (hi, lo) bf16 split of out
// ---------------------------------------------------------------------------
__global__ __launch_bounds__(128)
void add_ln_kernel(const float* __restrict__ X, const float* __restrict__ R,
                   const float* __restrict__ g, const float* __restrict__ bt,
                   float eps, float* __restrict__ out,
                   __nv_bfloat16* __restrict__ oh, __nv_bfloat16* __restrict__ ol,
                   int doSplit)
{
    const int row = blockIdx.x;
    const int tid = threadIdx.x;
    float4 v = *(const float4*)(X + (size_t)row * DMODEL + tid * 4);
    const float4 rr = *(const float4*)(R + (size_t)row * DMODEL + tid * 4);
    v.x += rr.x; v.y += rr.y; v.z += rr.z; v.w += rr.w;
    float s  = v.x + v.y + v.z + v.w;
    float sq = v.x * v.x + v.y * v.y + v.z * v.z + v.w * v.w;
#pragma unroll
    for (int off = 16; off; off >>= 1) {
        s  += __shfl_xor_sync(0xffffffffu, s,  off);
        sq += __shfl_xor_sync(0xffffffffu, sq, off);
    }
    __shared__ float ssum[4], ssq[4];
    const int w = tid >> 5, l = tid & 31;
    if (l == 0) { ssum[w] = s; ssq[w] = sq; }
    __syncthreads();
    s  = ssum[0] + ssum[1] + ssum[2] + ssum[3];
    sq = ssq[0]  + ssq[1]  + ssq[2]  + ssq[3];
    const float mean = s * (1.f / DMODEL);
    const float var  = sq * (1.f / DMODEL) - mean * mean;
    const float rstd = rsqrtf(var + eps);
    const float4 gg = *(const float4*)(g  + tid * 4);
    const float4 bb = *(const float4*)(bt + tid * 4);
    float4 r;
    r.x = (v.x - mean) * rstd * gg.x + bb.x;
    r.y = (v.y - mean) * rstd * gg.y + bb.y;
    r.z = (v.z - mean) * rstd * gg.z + bb.z;
    r.w = (v.w - mean) * rstd * gg.w + bb.w;
    *(float4*)(out + (size_t)row * DMODEL + tid * 4) = r;
    if (doSplit) {
        __nv_bfloat16 h0, h1, h2, h3, l0, l1, l2, l3;
        split2(r.x, h0, l0); split2(r.y, h1, l1);
        split2(r.z, h2, l2); split2(r.w, h3, l3);
        const size_t o = (size_t)row * DMODEL + tid * 4;
        *(__nv_bfloat162*)(oh + o)     = __nv_bfloat162(h0, h1);
        *(__nv_bfloat162*)(oh + o + 2) = __nv_bfloat162(h2, h3);
        *(__nv_bfloat162*)(ol + o)     = __nv_bfloat162(l0, l1);
        *(__nv_bfloat162*)(ol + o + 2) = __nv_bfloat162(l2, l3);
    }
}

// ---------------------------------------------------------------------------
// host side
// ---------------------------------------------------------------------------
static inline void do_split(const float* src, __nv_bfloat16* h, __nv_bfloat16* l, int n) {
    const int n4 = n / 4;
    split_kernel<<<(n4 + 255) / 256, 256>>>(src, h, l, n4);
}

extern "C" void kernel_launch(void* const* d_in, const int* in_sizes, int n_in,
                              void* d_out, int out_size)
{
    (void)in_sizes; (void)n_in; (void)out_size;
    const float* Fm   = (const float*)d_in[0];
    const float* Fs   = (const float*)d_in[1];
    const float* Fq   = (const float*)d_in[2];
    const float* Wq   = (const float*)d_in[3];
    const float* Wk   = (const float*)d_in[4];
    const float* Wv   = (const float*)d_in[5];
    const float* lng  = (const float*)d_in[6];
    const float* lnb  = (const float*)d_in[7];
    const float* w1   = (const float*)d_in[8];
    const float* w2   = (const float*)d_in[9];
    const float* flg  = (const float*)d_in[10];
    const float* flb  = (const float*)d_in[11];
    float* out = (float*)d_out;

    float *q, *k, *v, *att, *x, *y, *css, *cqq;
    cudaGetSymbolAddress((void**)&q,   g_q);
    cudaGetSymbolAddress((void**)&k,   g_k);
    cudaGetSymbolAddress((void**)&v,   g_v);
    cudaGetSymbolAddress((void**)&att, g_att);
    cudaGetSymbolAddress((void**)&x,   g_x);
    cudaGetSymbolAddress((void**)&y,   g_y);
    cudaGetSymbolAddress((void**)&css, g_css);
    cudaGetSymbolAddress((void**)&cqq, g_cqq);

    __nv_bfloat16 *wqh, *wql, *wkh, *wkl, *wvh, *wvl, *w1h, *w1l, *w2h, *w2l;
    __nv_bfloat16 *fmh, *fml, *fsh, *fsl, *fqh, *fql;
    __nv_bfloat16 *cssh, *cssl, *cqqh, *cqql, *xh, *xl, *hh, *hl;
    cudaGetSymbolAddress((void**)&wqh, g_wqh); cudaGetSymbolAddress((void**)&wql, g_wql);
    cudaGetSymbolAddress((void**)&wkh, g_wkh); cudaGetSymbolAddress((void**)&wkl, g_wkl);
    cudaGetSymbolAddress((void**)&wvh, g_wvh); cudaGetSymbolAddress((void**)&wvl, g_wvl);
    cudaGetSymbolAddress((void**)&w1h, g_w1h); cudaGetSymbolAddress((void**)&w1l, g_w1l);
    cudaGetSymbolAddress((void**)&w2h, g_w2h); cudaGetSymbolAddress((void**)&w2l, g_w2l);
    cudaGetSymbolAddress((void**)&fmh, g_fmh); cudaGetSymbolAddress((void**)&fml, g_fml);
    cudaGetSymbolAddress((void**)&fsh, g_fsh); cudaGetSymbolAddress((void**)&fsl, g_fsl);
    cudaGetSymbolAddress((void**)&fqh, g_fqh); cudaGetSymbolAddress((void**)&fql, g_fql);
    cudaGetSymbolAddress((void**)&cssh, g_cssh); cudaGetSymbolAddress((void**)&cssl, g_cssl);
    cudaGetSymbolAddress((void**)&cqqh, g_cqqh); cudaGetSymbolAddress((void**)&cqql, g_cqql);
    cudaGetSymbolAddress((void**)&xh, g_xh);   cudaGetSymbolAddress((void**)&xl, g_xl);
    cudaGetSymbolAddress((void**)&hh, g_hh);   cudaGetSymbolAddress((void**)&hl, g_hl);

    cudaFuncSetAttribute(flash_tc, cudaFuncAttributeMaxDynamicSharedMemorySize,
                         FA_SMEM_BYTES);
    cudaFuncSetAttribute(gemm_bf<0>, cudaFuncAttributeMaxDynamicSharedMemorySize,
                         GEMM_SMEM);
    cudaFuncSetAttribute(gemm_bf<1>, cudaFuncAttributeMaxDynamicSharedMemorySize,
                         GEMM_SMEM);

    // one-shot splits: weights + fixed inputs
    do_split(Wq, wqh, wql, 3 * DMODEL * DMODEL);
    do_split(Wk, wkh, wkl, 3 * DMODEL * DMODEL);
    do_split(Wv, wvh, wvl, 3 * DMODEL * DMODEL);
    do_split(w1, w1h, w1l, 3 * DHID * DMODEL);
    do_split(w2, w2h, w2l, 3 * DMODEL * DHID);
    do_split(Fm, fmh, fml, MTOT * DMODEL);
    do_split(Fs, fsh, fsl, MTOT * DMODEL);
    do_split(Fq, fqh, fql, MTOT * DMODEL);

    const dim3 gp(DMODEL / TBN, MTOT / TBM);   // (4, 64)
    const dim3 gh(DHID / TBN,   MTOT / TBM);   // (16, 64)
    const dim3 ga(SEQ / FM, NHEADS, BATCH);

    auto run_block = [&](int i,
                         const __nv_bfloat16* Qh, const __nv_bfloat16* Ql,
                         const __nv_bfloat16* Kh, const __nv_bfloat16* Kl,
                         const __nv_bfloat16* Vh, const __nv_bfloat16* Vl,
                         const float* Rp, float* op,
                         __nv_bfloat16* oph, __nv_bfloat16* opl, int splitOut) {
        const size_t wOff  = (size_t)i * DMODEL * DMODEL;
        const size_t w1Off = (size_t)i * DHID * DMODEL;
        gemm_bf<0><<<gp, 256, GEMM_SMEM>>>(Qh, Ql, wqh + wOff, wql + wOff,
                                           q, nullptr, nullptr, MTOT, DMODEL, DMODEL);
        gemm_bf<0><<<gp, 256, GEMM_SMEM>>>(Kh, Kl, wkh + wOff, wkl + wOff,
                                           k, nullptr, nullptr, MTOT, DMODEL, DMODEL);
        gemm_bf<0><<<gp, 256, GEMM_SMEM>>>(Vh, Vl, wvh + wOff, wvl + wOff,
                                           v, nullptr, nullptr, MTOT, DMODEL, DMODEL);
        flash_tc<<<ga, 128, FA_SMEM_BYTES>>>(q, k, v, att);
        add_ln_kernel<<<MTOT, 128>>>(att, Rp, lng + i * DMODEL, lnb + i * DMODEL,
                                     1e-5f, x, xh, xl, 1);
        gemm_bf<1><<<gh, 256, GEMM_SMEM>>>(xh, xl, w1h + w1Off, w1l + w1Off,
                                           nullptr, hh, hl, MTOT, DHID, DMODEL);
        gemm_bf<0><<<gp, 256, GEMM_SMEM>>>(hh, hl, w2h + w1Off, w2l + w1Off,
                                           y, nullptr, nullptr, MTOT, DMODEL, DHID);
        add_ln_kernel<<<MTOT, 128>>>(y, x, flg + i * DMODEL, flb + i * DMODEL,
                                     1e-6f, op, oph, opl, splitOut);
    };

    // css = blk(0, Fs, Fs, Fm, Fm); cqq = blk(1, Fq, Fq, Fq, Fq);
    // csq = blk(2, cqq, Fs, css, css)
    run_block(0, fsh, fsl, fsh, fsl, fmh, fml, Fm, css, cssh, cssl, 1);
    run_block(1, fqh, fql, fqh, fql, fqh, fql, Fq, cqq, cqqh, cqql, 1);
    run_block(2, cqqh, cqql, fsh, fsl, cssh, cssl, css, out, nullptr, nullptr, 0);
}

// round 10
// speedup vs baseline: 4.4480x; 1.1153x over previous
#include <cuda_runtime.h>
#include <cuda_bf16.h>
#include <cstdint>

// ---------------------------------------------------------------------------
// Problem constants
// ---------------------------------------------------------------------------
#define BATCH   4
#define SEQ     2048
#define DMODEL  512
#define DHID    2048
#define NHEADS  2
#define GSZ     256
#define MTOT    (BATCH * SEQ)       // 8192

// ---------------------------------------------------------------------------
// Scratch (device globals)
// ---------------------------------------------------------------------------
__device__ float g_q  [MTOT * DMODEL];
__device__ float g_k  [MTOT * DMODEL];
__device__ float g_v  [MTOT * DMODEL];
__device__ float g_att[MTOT * DMODEL];
__device__ float g_x  [MTOT * DMODEL];
__device__ float g_y  [MTOT * DMODEL];
__device__ float g_css[MTOT * DMODEL];
__device__ float g_cqq[MTOT * DMODEL];

__device__ __nv_bfloat16 g_wqh[3*DMODEL*DMODEL], g_wql[3*DMODEL*DMODEL];
__device__ __nv_bfloat16 g_wkh[3*DMODEL*DMODEL], g_wkl[3*DMODEL*DMODEL];
__device__ __nv_bfloat16 g_wvh[3*DMODEL*DMODEL], g_wvl[3*DMODEL*DMODEL];
__device__ __nv_bfloat16 g_w1h[3*DHID*DMODEL],   g_w1l[3*DHID*DMODEL];
__device__ __nv_bfloat16 g_w2h[3*DMODEL*DHID],   g_w2l[3*DMODEL*DHID];
__device__ __nv_bfloat16 g_fmh[MTOT*DMODEL], g_fml[MTOT*DMODEL];
__device__ __nv_bfloat16 g_fsh[MTOT*DMODEL], g_fsl[MTOT*DMODEL];
__device__ __nv_bfloat16 g_fqh[MTOT*DMODEL], g_fql[MTOT*DMODEL];
__device__ __nv_bfloat16 g_cssh[MTOT*DMODEL], g_cssl[MTOT*DMODEL];
__device__ __nv_bfloat16 g_cqqh[MTOT*DMODEL], g_cqql[MTOT*DMODEL];
__device__ __nv_bfloat16 g_xh[MTOT*DMODEL],  g_xl[MTOT*DMODEL];
__device__ __nv_bfloat16 g_hh[MTOT*DHID],    g_hl[MTOT*DHID];

// ---------------------------------------------------------------------------
// helpers
// ---------------------------------------------------------------------------
__device__ __forceinline__ uint32_t sptr(const void* p) {
    return (uint32_t)__cvta_generic_to_shared(p);
}
__device__ __forceinline__ void ldm4(uint32_t a, uint32_t& r0, uint32_t& r1,
                                     uint32_t& r2, uint32_t& r3) {
    asm volatile("ldmatrix.sync.aligned.m8n8.x4.shared.b16 {%0,%1,%2,%3},[%4];"
                 : "=r"(r0), "=r"(r1), "=r"(r2), "=r"(r3) : "r"(a));
}
__device__ __forceinline__ void mma_bf16(float c[4], const uint32_t a[4],
                                         const uint32_t b[2]) {
    asm volatile(
        "mma.sync.aligned.m16n8k16.row.col.f32.bf16.bf16.f32 "
        "{%0,%1,%2,%3},{%4,%5,%6,%7},{%8,%9},{%0,%1,%2,%3};"
        : "+f"(c[0]), "+f"(c[1]), "+f"(c[2]), "+f"(c[3])
        : "r"(a[0]), "r"(a[1]), "r"(a[2]), "r"(a[3]), "r"(b[0]), "r"(b[1]));
}
__device__ __forceinline__ float e2(float x) {
    float y; asm("ex2.approx.ftz.f32 %0,%1;" : "=f"(y) : "f"(x)); return y;
}
__device__ __forceinline__ uint32_t packbf(float a, float b) {
    const __nv_bfloat162 t = __float22bfloat162_rn(make_float2(a, b));
    return *reinterpret_cast<const uint32_t*>(&t);
}
__device__ __forceinline__ void split2(float v, __nv_bfloat16& h, __nv_bfloat16& l) {
    h = __float2bfloat16(v);
    l = __float2bfloat16(v - __bfloat162float(h));
}
__device__ __forceinline__ void cpa16(uint32_t s, const void* g) {
    asm volatile("cp.async.cg.shared.global [%0],[%1],16;" :: "r"(s), "l"(g));
}
__device__ __forceinline__ void cpa_commit() {
    asm volatile("cp.async.commit_group;");
}
template <int N>
__device__ __forceinline__ void cpa_wait() {
    asm volatile("cp.async.wait_group %0;" :: "n"(N));
}

// ---------------------------------------------------------------------------
// split kernel: fp32 -> (hi, lo) bf16
// ---------------------------------------------------------------------------
__global__ __launch_bounds__(256)
void split_kernel(const float* __restrict__ src, __nv_bfloat16* __restrict__ h,
                  __nv_bfloat16* __restrict__ l, int n4)
{
    const int i = blockIdx.x * 256 + threadIdx.x;
    if (i >= n4) return;
    const float4 v = *(const float4*)(src + (size_t)i * 4);
    __nv_bfloat16 h0, h1, h2, h3, l0, l1, l2, l3;
    split2(v.x, h0, l0); split2(v.y, h1, l1);
    split2(v.z, h2, l2); split2(v.w, h3, l3);
    *(__nv_bfloat162*)(h + (size_t)i * 4)     = __nv_bfloat162(h0, h1);
    *(__nv_bfloat162*)(h + (size_t)i * 4 + 2) = __nv_bfloat162(h2, h3);
    *(__nv_bfloat162*)(l + (size_t)i * 4)     = __nv_bfloat162(l0, l1);
    *(__nv_bfloat162*)(l + (size_t)i * 4 + 2) = __nv_bfloat162(l2, l3);
}

// ---------------------------------------------------------------------------
// Pure-bf16 split GEMM:  C = epi( (Ah+Al)[M,K] @ (Bh+Bl)[N,K]^T )
// 128x128x32 CTA tile, 4 warps (each 64x64), cp.async double-buffered.
// 3-pass split accumulation: hi*hi + hi*lo + lo*hi.
// OUT: 0 -> fp32 C;  1 -> relu + split to (Ch, Cl) bf16
// ---------------------------------------------------------------------------
#define TBM 128
#define TBN 128
#define TBK 32
#define TAS 40
#define REGB  (TBM * TAS * 2)      // 10240 bytes per matrix region
#define BUFSZ (4 * REGB)           // Ah | Al | Bh | Bl  = 40960
#define GEMM_SMEM (2 * BUFSZ)      // 81920 -> 2 CTAs/SM

extern __shared__ char gsm[];

template <int OUT>
__global__ __launch_bounds__(128, 2)
void gemm_bf(const __nv_bfloat16* __restrict__ Agh, const __nv_bfloat16* __restrict__ Agl,
             const __nv_bfloat16* __restrict__ Bgh, const __nv_bfloat16* __restrict__ Bgl,
             float* __restrict__ C, __nv_bfloat16* __restrict__ Ch,
             __nv_bfloat16* __restrict__ Cl, int M, int N, int K)
{
    const int tid  = threadIdx.x;
    const int lane = tid & 31;
    const int wid  = tid >> 5;
    const int wm   = wid & 1;        // 2 m-warps * 64 rows
    const int wn   = wid >> 1;       // 2 n-warps * 64 cols
    const int bm   = blockIdx.y * TBM;
    const int bn   = blockIdx.x * TBN;

    const uint32_t sbase = sptr(gsm);

    // loader: 512 16B-chunks per region, 4 per thread per region
    auto load_tile = [&](int buf, int k0) {
        const uint32_t b = sbase + buf * BUFSZ;
#pragma unroll
        for (int j = 0; j < 4; ++j) {
            const int c = tid + j * 128;           // 0..511
            const int row = c >> 2, kc = (c & 3) << 3;
            const uint32_t so = (uint32_t)(row * TAS + kc) * 2;
            const size_t goA = (size_t)(bm + row) * K + k0 + kc;
            const size_t goB = (size_t)(bn + row) * K + k0 + kc;
            cpa16(b + so,            Agh + goA);
            cpa16(b + REGB + so,     Agl + goA);
            cpa16(b + 2 * REGB + so, Bgh + goB);
            cpa16(b + 3 * REGB + so, Bgl + goB);
        }
        cpa_commit();
    };

    float c[4][8][4];
#pragma unroll
    for (int mi = 0; mi < 4; ++mi)
#pragma unroll
        for (int ni = 0; ni < 8; ++ni)
#pragma unroll
            for (int e = 0; e < 4; ++e) c[mi][ni][e] = 0.f;

    // fragment lane geometry (validated pattern)
    const int lmA = lane & 15;
    const int lkA = (lane >> 4) << 3;
    const int lnB = ((lane >> 4) & 1) * 8 + (lane & 7);
    const int lkB = ((lane >> 3) & 1) * 8;
    const uint32_t relA = (uint32_t)((wm * 64 + lmA) * TAS + lkA) * 2;
    const uint32_t relB = (uint32_t)((wn * 64 + lnB) * TAS + lkB) * 2;

    const int niter = K / TBK;
    load_tile(0, 0);

    for (int it = 0; it < niter; ++it) {
        const int cur = it & 1;
        if (it + 1 < niter) { load_tile(cur ^ 1, (it + 1) * TBK); cpa_wait<1>(); }
        else cpa_wait<0>();
        __syncthreads();

        const uint32_t b = sbase + cur * BUFSZ;
        const uint32_t aAh = b + relA,            aAl = b + REGB + relA;
        const uint32_t aBh = b + 2 * REGB + relB, aBl = b + 3 * REGB + relB;

#pragma unroll
        for (int ks = 0; ks < 2; ++ks) {
            const uint32_t ko = ks * 32;     // 16 bf16 = 32 bytes
            // B fragments for full n64 (hi + lo), resident across mi loop
            uint32_t bhf[8][2], blf[8][2];
#pragma unroll
            for (int p = 0; p < 4; ++p) {
                ldm4(aBh + p * (16 * TAS * 2) + ko,
                     bhf[2*p][0], bhf[2*p][1], bhf[2*p+1][0], bhf[2*p+1][1]);
                ldm4(aBl + p * (16 * TAS * 2) + ko,
                     blf[2*p][0], blf[2*p][1], blf[2*p+1][0], blf[2*p+1][1]);
            }
#pragma unroll
            for (int mi = 0; mi < 4; ++mi) {
                uint32_t ah[4], al[4];
                ldm4(aAh + mi * (16 * TAS * 2) + ko, ah[0], ah[1], ah[2], ah[3]);
                ldm4(aAl + mi * (16 * TAS * 2) + ko, al[0], al[1], al[2], al[3]);
                // three independent 8-wide sweeps: no back-to-back RAW on c
#pragma unroll
                for (int ni = 0; ni < 8; ++ni) mma_bf16(c[mi][ni], ah, bhf[ni]);
#pragma unroll
                for (int ni = 0; ni < 8; ++ni) mma_bf16(c[mi][ni], ah, blf[ni]);
#pragma unroll
                for (int ni = 0; ni < 8; ++ni) mma_bf16(c[mi][ni], al, bhf[ni]);
            }
        }
        __syncthreads();
    }

    // epilogue
#pragma unroll
    for (int mi = 0; mi < 4; ++mi) {
        const int row0 = bm + wm * 64 + mi * 16 + (lane >> 2);
#pragma unroll
        for (int ni = 0; ni < 8; ++ni) {
            const int col = bn + wn * 64 + ni * 8 + ((lane & 3) << 1);
            float v0 = c[mi][ni][0], v1 = c[mi][ni][1];
            float v2 = c[mi][ni][2], v3 = c[mi][ni][3];
            if (OUT == 0) {
                float2 a; a.x = v0; a.y = v1;
                float2 bq; bq.x = v2; bq.y = v3;
                *(float2*)&C[(size_t)row0 * N + col]       = a;
                *(float2*)&C[(size_t)(row0 + 8) * N + col] = bq;
            } else {
                v0 = fmaxf(v0, 0.f); v1 = fmaxf(v1, 0.f);
                v2 = fmaxf(v2, 0.f); v3 = fmaxf(v3, 0.f);
                __nv_bfloat16 h0, h1, h2, h3, l0, l1, l2, l3;
                split2(v0, h0, l0); split2(v1, h1, l1);
                split2(v2, h2, l2); split2(v3, h3, l3);
                *(__nv_bfloat162*)&Ch[(size_t)row0 * N + col]       = __nv_bfloat162(h0, h1);
                *(__nv_bfloat162*)&Cl[(size_t)row0 * N + col]       = __nv_bfloat162(l0, l1);
                *(__nv_bfloat162*)&Ch[(size_t)(row0 + 8) * N + col] = __nv_bfloat162(h2, h3);
                *(__nv_bfloat162*)&Cl[(size_t)(row0 + 8) * N + col] = __nv_bfloat162(l2, l3);
            }
        }
    }
}

// ---------------------------------------------------------------------------
// Tensor-core flash attention (mma.sync, validated @336us)
// ---------------------------------------------------------------------------
#define FM  64
#define FN  64
#define FQS 264
#define VTS 72
#define FA_SMEM_BYTES ((FM*FQS + FN*FQS + GSZ*VTS) * 2)

extern __shared__ char fa_raw[];

__global__ __launch_bounds__(128, 2)
void flash_tc(const float* __restrict__ Q, const float* __restrict__ K,
              const float* __restrict__ V, float* __restrict__ O)
{
    __nv_bfloat16* Qs = (__nv_bfloat16*)fa_raw;
    __nv_bfloat16* Ks = Qs + FM * FQS;
    __nv_bfloat16* Vt = Ks + FN * FQS;

    const int tid  = threadIdx.x;
    const int lane = tid & 31;
    const int w    = tid >> 5;
    const int qbase = blockIdx.x * FM;
    const int h = blockIdx.y, b = blockIdx.z;
    const size_t bstride = (size_t)SEQ * DMODEL;
    const float* Qb = Q + b * bstride + h * GSZ;
    const float* Kb = K + b * bstride + h * GSZ;
    const float* Vb = V + b * bstride + h * GSZ;

    const int lmA = lane & 15;
    const int lkA = (lane >> 4) << 3;
    const int lnB = ((lane >> 4) & 1) * 8 + (lane & 7);
    const int lkB = ((lane >> 3) & 1) * 8;

    const uint32_t aQ = sptr(Qs) + (uint32_t)((w * 16 + lmA) * FQS + lkA) * 2;
    const uint32_t aK = sptr(Ks) + (uint32_t)(lnB * FQS + lkB) * 2;
    const uint32_t aV = sptr(Vt) + (uint32_t)(lnB * VTS + lkB) * 2;

    const float qscale = 0.0625f * 1.4426950408889634f;
    for (int j = 0; j < 32; ++j) {
        const int idx = tid + j * 128;
        const int row = idx >> 6, f4 = idx & 63;
        const float4 v = *(const float4*)(Qb + (size_t)(qbase + row) * DMODEL + f4 * 4);
        __nv_bfloat16* p = Qs + row * FQS + f4 * 4;
        *(__nv_bfloat162*)(p)     = __float22bfloat162_rn(make_float2(v.x * qscale, v.y * qscale));
        *(__nv_bfloat162*)(p + 2) = __float22bfloat162_rn(make_float2(v.z * qscale, v.w * qscale));
    }

    float mA = -1e30f, mB = -1e30f, lA = 0.f, lB = 0.f;
    float o[32][4];
#pragma unroll
    for (int f = 0; f < 32; ++f)
#pragma unroll
        for (int e = 0; e < 4; ++e) o[f][e] = 0.f;

    const int vkcol = tid & 63;
    const int vdch  = tid >> 6;

    for (int kb = 0; kb < SEQ; kb += FN) {
        __syncthreads();
        for (int j = 0; j < 32; ++j) {
            const int idx = tid + j * 128;
            const int row = idx >> 6, f4 = idx & 63;
            const float4 v = *(const float4*)(Kb + (size_t)(kb + row) * DMODEL + f4 * 4);
            __nv_bfloat16* p = Ks + row * FQS + f4 * 4;
            *(__nv_bfloat162*)(p)     = __float22bfloat162_rn(make_float2(v.x, v.y));
            *(__nv_bfloat162*)(p + 2) = __float22bfloat162_rn(make_float2(v.z, v.w));
        }
        {
            const float* vsrc = Vb + (size_t)(kb + vkcol) * DMODEL + vdch * 128;
#pragma unroll
            for (int j = 0; j < 32; ++j) {
                const float4 v = *(const float4*)(vsrc + j * 4);
                const int d = vdch * 128 + j * 4;
                Vt[(d + 0) * VTS + vkcol] = __float2bfloat16(v.x);
                Vt[(d + 1) * VTS + vkcol] = __float2bfloat16(v.y);
                Vt[(d + 2) * VTS + vkcol] = __float2bfloat16(v.z);
                Vt[(d + 3) * VTS + vkcol] = __float2bfloat16(v.w);
            }
        }
        __syncthreads();

        float s[8][4];
#pragma unroll
        for (int f = 0; f < 8; ++f)
#pragma unroll
            for (int e = 0; e < 4; ++e) s[f][e] = 0.f;

#pragma unroll
        for (int ks = 0; ks < 16; ++ks) {
            uint32_t af[4];
            ldm4(aQ + ks * 32, af[0], af[1], af[2], af[3]);
#pragma unroll
            for (int g = 0; g < 4; ++g) {
                uint32_t b0[2], b1[2];
                ldm4(aK + (uint32_t)(g * 16 * FQS) * 2 + ks * 32,
                     b0[0], b0[1], b1[0], b1[1]);
                mma_bf16(s[2 * g],     af, b0);
                mma_bf16(s[2 * g + 1], af, b1);
            }
        }

        float mxA = -1e30f, mxB = -1e30f;
#pragma unroll
        for (int f = 0; f < 8; ++f) {
            mxA = fmaxf(mxA, fmaxf(s[f][0], s[f][1]));
            mxB = fmaxf(mxB, fmaxf(s[f][2], s[f][3]));
        }
        mxA = fmaxf(mxA, __shfl_xor_sync(0xffffffffu, mxA, 1));
        mxA = fmaxf(mxA, __shfl_xor_sync(0xffffffffu, mxA, 2));
        mxB = fmaxf(mxB, __shfl_xor_sync(0xffffffffu, mxB, 1));
        mxB = fmaxf(mxB, __shfl_xor_sync(0xffffffffu, mxB, 2));
        const float mnA = fmaxf(mA, mxA);
        const float mnB = fmaxf(mB, mxB);
        float sumA = 0.f, sumB = 0.f;
#pragma unroll
        for (int f = 0; f < 8; ++f) {
            s[f][0] = e2(s[f][0] - mnA); s[f][1] = e2(s[f][1] - mnA);
            s[f][2] = e2(s[f][2] - mnB); s[f][3] = e2(s[f][3] - mnB);
            sumA += s[f][0] + s[f][1];
            sumB += s[f][2] + s[f][3];
        }
        sumA += __shfl_xor_sync(0xffffffffu, sumA, 1);
        sumA += __shfl_xor_sync(0xffffffffu, sumA, 2);
        sumB += __shfl_xor_sync(0xffffffffu, sumB, 1);
        sumB += __shfl_xor_sync(0xffffffffu, sumB, 2);
        const float ccA = e2(mA - mnA);
        const float ccB = e2(mB - mnB);
        lA = lA * ccA + sumA; mA = mnA;
        lB = lB * ccB + sumB; mB = mnB;

#pragma unroll
        for (int f = 0; f < 32; ++f) {
            o[f][0] *= ccA; o[f][1] *= ccA;
            o[f][2] *= ccB; o[f][3] *= ccB;
        }

#pragma unroll
        for (int kf = 0; kf < 4; ++kf) {
            uint32_t ap[4];
            ap[0] = packbf(s[2 * kf][0],     s[2 * kf][1]);
            ap[1] = packbf(s[2 * kf][2],     s[2 * kf][3]);
            ap[2] = packbf(s[2 * kf + 1][0], s[2 * kf + 1][1]);
            ap[3] = packbf(s[2 * kf + 1][2], s[2 * kf + 1][3]);
#pragma unroll
            for (int g = 0; g < 16; ++g) {
                uint32_t b0[2], b1[2];
                ldm4(aV + (uint32_t)(g * 16 * VTS) * 2 + kf * 32,
                     b0[0], b0[1], b1[0], b1[1]);
                mma_bf16(o[2 * g],     ap, b0);
                mma_bf16(o[2 * g + 1], ap, b1);
            }
        }
    }

    const float liA = 1.f / lA;
    const float liB = 1.f / lB;
    const int rowA = qbase + w * 16 + (lane >> 2);
    float* Ob = O + b * bstride + h * GSZ;
#pragma unroll
    for (int f = 0; f < 32; ++f) {
        const int col = f * 8 + ((lane & 3) << 1);
        float2 rA; rA.x = o[f][0] * liA; rA.y = o[f][1] * liA;
        float2 rB; rB.x = o[f][2] * liB; rB.y = o[f][3] * liB;
        *(float2*)&Ob[(size_t)rowA * DMODEL + col]       = rA;
        *(float2*)&Ob[(size_t)(rowA + 8) * DMODEL + col] = rB;
    }
}

// ---------------------------------------------------------------------------
// out = LayerNorm(X + R); optionally also emit (hi, lo) bf16 split
// ---------------------------------------------------------------------------
__global__ __launch_bounds__(128)
void add_ln_kernel(const float* __restrict__ X, const float* __restrict__ R,
                   const float* __restrict__ g, const float* __restrict__ bt,
                   float eps, float* __restrict__ out,
                   __nv_bfloat16* __restrict__ oh, __nv_bfloat16* __restrict__ ol,
                   int doSplit)
{
    const int row = blockIdx.x;
    const int tid = threadIdx.x;
    float4 v = *(const float4*)(X + (size_t)row * DMODEL + tid * 4);
    const float4 rr = *(const float4*)(R + (size_t)row * DMODEL + tid * 4);
    v.x += rr.x; v.y += rr.y; v.z += rr.z; v.w += rr.w;
    float s  = v.x + v.y + v.z + v.w;
    float sq = v.x * v.x + v.y * v.y + v.z * v.z + v.w * v.w;
#pragma unroll
    for (int off = 16; off; off >>= 1) {
        s  += __shfl_xor_sync(0xffffffffu, s,  off);
        sq += __shfl_xor_sync(0xffffffffu, sq, off);
    }
    __shared__ float ssum[4], ssq[4];
    const int w = tid >> 5, l = tid & 31;
    if (l == 0) { ssum[w] = s; ssq[w] = sq; }
    __syncthreads();
    s  = ssum[0] + ssum[1] + ssum[2] + ssum[3];
    sq = ssq[0]  + ssq[1]  + ssq[2]  + ssq[3];
    const float mean = s * (1.f / DMODEL);
    const float var  = sq * (1.f / DMODEL) - mean * mean;
    const float rstd = rsqrtf(var + eps);
    const float4 gg = *(const float4*)(g  + tid * 4);
    const float4 bb = *(const float4*)(bt + tid * 4);
    float4 r;
    r.x = (v.x - mean) * rstd * gg.x + bb.x;
    r.y = (v.y - mean) * rstd * gg.y + bb.y;
    r.z = (v.z - mean) * rstd * gg.z + bb.z;
    r.w = (v.w - mean) * rstd * gg.w + bb.w;
    *(float4*)(out + (size_t)row * DMODEL + tid * 4) = r;
    if (doSplit) {
        __nv_bfloat16 h0, h1, h2, h3, l0, l1, l2, l3;
        split2(r.x, h0, l0); split2(r.y, h1, l1);
        split2(r.z, h2, l2); split2(r.w, h3, l3);
        const size_t o = (size_t)row * DMODEL + tid * 4;
        *(__nv_bfloat162*)(oh + o)     = __nv_bfloat162(h0, h1);
        *(__nv_bfloat162*)(oh + o + 2) = __nv_bfloat162(h2, h3);
        *(__nv_bfloat162*)(ol + o)     = __nv_bfloat162(l0, l1);
        *(__nv_bfloat162*)(ol + o + 2) = __nv_bfloat162(l2, l3);
    }
}

// ---------------------------------------------------------------------------
// host side
// ---------------------------------------------------------------------------
static inline void do_split(const float* src, __nv_bfloat16* h, __nv_bfloat16* l, int n) {
    const int n4 = n / 4;
    split_kernel<<<(n4 + 255) / 256, 256>>>(src, h, l, n4);
}

extern "C" void kernel_launch(void* const* d_in, const int* in_sizes, int n_in,
                              void* d_out, int out_size)
{
    (void)in_sizes; (void)n_in; (void)out_size;
    const float* Fm   = (const float*)d_in[0];
    const float* Fs   = (const float*)d_in[1];
    const float* Fq   = (const float*)d_in[2];
    const float* Wq   = (const float*)d_in[3];
    const float* Wk   = (const float*)d_in[4];
    const float* Wv   = (const float*)d_in[5];
    const float* lng  = (const float*)d_in[6];
    const float* lnb  = (const float*)d_in[7];
    const float* w1   = (const float*)d_in[8];
    const float* w2   = (const float*)d_in[9];
    const float* flg  = (const float*)d_in[10];
    const float* flb  = (const float*)d_in[11];
    float* out = (float*)d_out;

    float *q, *k, *v, *att, *x, *y, *css, *cqq;
    cudaGetSymbolAddress((void**)&q,   g_q);
    cudaGetSymbolAddress((void**)&k,   g_k);
    cudaGetSymbolAddress((void**)&v,   g_v);
    cudaGetSymbolAddress((void**)&att, g_att);
    cudaGetSymbolAddress((void**)&x,   g_x);
    cudaGetSymbolAddress((void**)&y,   g_y);
    cudaGetSymbolAddress((void**)&css, g_css);
    cudaGetSymbolAddress((void**)&cqq, g_cqq);

    __nv_bfloat16 *wqh, *wql, *wkh, *wkl, *wvh, *wvl, *w1h, *w1l, *w2h, *w2l;
    __nv_bfloat16 *fmh, *fml, *fsh, *fsl, *fqh, *fql;
    __nv_bfloat16 *cssh, *cssl, *cqqh, *cqql, *xh, *xl, *hh, *hl;
    cudaGetSymbolAddress((void**)&wqh, g_wqh); cudaGetSymbolAddress((void**)&wql, g_wql);
    cudaGetSymbolAddress((void**)&wkh, g_wkh); cudaGetSymbolAddress((void**)&wkl, g_wkl);
    cudaGetSymbolAddress((void**)&wvh, g_wvh); cudaGetSymbolAddress((void**)&wvl, g_wvl);
    cudaGetSymbolAddress((void**)&w1h, g_w1h); cudaGetSymbolAddress((void**)&w1l, g_w1l);
    cudaGetSymbolAddress((void**)&w2h, g_w2h); cudaGetSymbolAddress((void**)&w2l, g_w2l);
    cudaGetSymbolAddress((void**)&fmh, g_fmh); cudaGetSymbolAddress((void**)&fml, g_fml);
    cudaGetSymbolAddress((void**)&fsh, g_fsh); cudaGetSymbolAddress((void**)&fsl, g_fsl);
    cudaGetSymbolAddress((void**)&fqh, g_fqh); cudaGetSymbolAddress((void**)&fql, g_fql);
    cudaGetSymbolAddress((void**)&cssh, g_cssh); cudaGetSymbolAddress((void**)&cssl, g_cssl);
    cudaGetSymbolAddress((void**)&cqqh, g_cqqh); cudaGetSymbolAddress((void**)&cqql, g_cqql);
    cudaGetSymbolAddress((void**)&xh, g_xh);   cudaGetSymbolAddress((void**)&xl, g_xl);
    cudaGetSymbolAddress((void**)&hh, g_hh);   cudaGetSymbolAddress((void**)&hl, g_hl);

    cudaFuncSetAttribute(flash_tc, cudaFuncAttributeMaxDynamicSharedMemorySize,
                         FA_SMEM_BYTES);
    cudaFuncSetAttribute(gemm_bf<0>, cudaFuncAttributeMaxDynamicSharedMemorySize,
                         GEMM_SMEM);
    cudaFuncSetAttribute(gemm_bf<1>, cudaFuncAttributeMaxDynamicSharedMemorySize,
                         GEMM_SMEM);

    do_split(Wq, wqh, wql, 3 * DMODEL * DMODEL);
    do_split(Wk, wkh, wkl, 3 * DMODEL * DMODEL);
    do_split(Wv, wvh, wvl, 3 * DMODEL * DMODEL);
    do_split(w1, w1h, w1l, 3 * DHID * DMODEL);
    do_split(w2, w2h, w2l, 3 * DMODEL * DHID);
    do_split(Fm, fmh, fml, MTOT * DMODEL);
    do_split(Fs, fsh, fsl, MTOT * DMODEL);
    do_split(Fq, fqh, fql, MTOT * DMODEL);

    const dim3 gp(DMODEL / TBN, MTOT / TBM);   // (4, 64)
    const dim3 gh(DHID / TBN,   MTOT / TBM);   // (16, 64)
    const dim3 ga(SEQ / FM, NHEADS, BATCH);

    auto run_block = [&](int i,
                         const __nv_bfloat16* Qh, const __nv_bfloat16* Ql,
                         const __nv_bfloat16* Kh, const __nv_bfloat16* Kl,
                         const __nv_bfloat16* Vh, const __nv_bfloat16* Vl,
                         const float* Rp, float* op,
                         __nv_bfloat16* oph, __nv_bfloat16* opl, int splitOut) {
        const size_t wOff  = (size_t)i * DMODEL * DMODEL;
        const size_t w1Off = (size_t)i * DHID * DMODEL;
        gemm_bf<0><<<gp, 128, GEMM_SMEM>>>(Qh, Ql, wqh + wOff, wql + wOff,
                                           q, nullptr, nullptr, MTOT, DMODEL, DMODEL);
        gemm_bf<0><<<gp, 128, GEMM_SMEM>>>(Kh, Kl, wkh + wOff, wkl + wOff,
                                           k, nullptr, nullptr, MTOT, DMODEL, DMODEL);
        gemm_bf<0><<<gp, 128, GEMM_SMEM>>>(Vh, Vl, wvh + wOff, wvl + wOff,
                                           v, nullptr, nullptr, MTOT, DMODEL, DMODEL);
        flash_tc<<<ga, 128, FA_SMEM_BYTES>>>(q, k, v, att);
        add_ln_kernel<<<MTOT, 128>>>(att, Rp, lng + i * DMODEL, lnb + i * DMODEL,
                                     1e-5f, x, xh, xl, 1);
        gemm_bf<1><<<gh, 128, GEMM_SMEM>>>(xh, xl, w1h + w1Off, w1l + w1Off,
                                           nullptr, hh, hl, MTOT, DHID, DMODEL);
        gemm_bf<0><<<gp, 128, GEMM_SMEM>>>(hh, hl, w2h + w1Off, w2l + w1Off,
                                           y, nullptr, nullptr, MTOT, DMODEL, DHID);
        add_ln_kernel<<<MTOT, 128>>>(y, x, flg + i * DMODEL, flb + i * DMODEL,
                                     1e-6f, op, oph, opl, splitOut);
    };

    run_block(0, fsh, fsl, fsh, fsl, fmh, fml, Fm, css, cssh, cssl, 1);
    run_block(1, fqh, fql, fqh, fql, fqh, fql, Fq, cqq, cqqh, cqql, 1);
    run_block(2, cqqh, cqql, fsh, fsl, cssh, cssl, css, out, nullptr, nullptr, 0);
}